// round 11
// baseline (speedup 1.0000x reference)
#include <cuda_runtime.h>
#include <cuda_fp16.h>
#include <math.h>
#include <stdint.h>

// Problem dims (fixed by the reference)
#define TT 2048   // tokens
#define EE 2048   // embed
#define HH 16     // heads
#define LL 512    // latent
#define DD 128    // head dim
#define RA_WIN 64

typedef __half f16;
typedef __half2 f162;

// ---------------- scratch (allocation-free: device globals) ----------------
__device__ f16 g_hidh[TT * EE],  g_hidl[TT * EE];
__device__ f16 g_wqh[EE * EE];
__device__ f16 g_wkdh[LL * EE];
__device__ f16 g_wvdh[LL * EE];
__device__ f16 g_wouth[EE * EE];
__device__ f16 g_q2lTh[HH * LL * DD];          // [H][L][D]
__device__ f16 g_vupTh[HH * DD * LL];          // [H][D][L]
__device__ f16 g_Qh[TT * EE],   g_Ql[TT * EE];
__device__ f16 g_latkh[TT * LL];
__device__ f16 g_latvh[TT * LL], g_latvl[TT * LL];
__device__ f16 g_qlath[(size_t)HH * TT * LL], g_qlatl[(size_t)HH * TT * LL];
__device__ f16 g_Vh[TT * EE];                  // [T][H*D]
__device__ f16 g_VTh[EE * TT];                 // [H*D][T]
__device__ f16 g_Sh[(size_t)HH * TT * TT], g_Sl[(size_t)HH * TT * TT];
__device__ f16 g_ctxh[TT * EE];

// ---------------- helpers ----------------
__device__ __forceinline__ uint32_t smem_u32(const void* p) {
    uint32_t a;
    asm("{ .reg .u64 t; cvta.to.shared.u64 t, %1; cvt.u32.u64 %0, t; }"
        : "=r"(a) : "l"(p));
    return a;
}

__device__ __forceinline__ void cp16(uint32_t dst, const void* src) {
    asm volatile("cp.async.cg.shared.global [%0], [%1], 16;" :: "r"(dst), "l"(src));
}
__device__ __forceinline__ void cp_commit() {
    asm volatile("cp.async.commit_group;" ::: "memory");
}
template <int N>
__device__ __forceinline__ void cp_wait() {
    asm volatile("cp.async.wait_group %0;" :: "n"(N) : "memory");
}

__device__ __forceinline__ void ldsm_x4(uint32_t& r0, uint32_t& r1,
                                        uint32_t& r2, uint32_t& r3,
                                        uint32_t addr) {
    asm volatile("ldmatrix.sync.aligned.m8n8.x4.shared.b16 {%0,%1,%2,%3}, [%4];\n"
                 : "=r"(r0), "=r"(r1), "=r"(r2), "=r"(r3)
                 : "r"(addr));
}

__device__ __forceinline__ void mma_f16(float& c0, float& c1, float& c2, float& c3,
                                        uint32_t a0, uint32_t a1, uint32_t a2, uint32_t a3,
                                        uint32_t b0, uint32_t b1) {
    asm volatile("mma.sync.aligned.m16n8k16.row.col.f32.f16.f16.f32 "
                 "{%0,%1,%2,%3}, {%4,%5,%6,%7}, {%8,%9}, {%0,%1,%2,%3};\n"
                 : "+f"(c0), "+f"(c1), "+f"(c2), "+f"(c3)
                 : "r"(a0), "r"(a1), "r"(a2), "r"(a3), "r"(b0), "r"(b1));
}

// ---------------- conversion kernels ----------------
__global__ __launch_bounds__(256)
void split_k(const float* __restrict__ in, f16* __restrict__ h,
             f16* __restrict__ l, int n4)
{
    int i = blockIdx.x * blockDim.x + threadIdx.x;
    if (i >= n4) return;
    float4 v = ((const float4*)in)[i];
    f16 hx = __float2half(v.x), hy = __float2half(v.y);
    f16 hz = __float2half(v.z), hw = __float2half(v.w);
    ((f162*)h)[2 * i]     = __halves2half2(hx, hy);
    ((f162*)h)[2 * i + 1] = __halves2half2(hz, hw);
    ((f162*)l)[2 * i] = __halves2half2(
        __float2half(v.x - __half2float(hx)),
        __float2half(v.y - __half2float(hy)));
    ((f162*)l)[2 * i + 1] = __halves2half2(
        __float2half(v.z - __half2float(hz)),
        __float2half(v.w - __half2float(hw)));
}

__global__ __launch_bounds__(256)
void split_k1(const float* __restrict__ in, f16* __restrict__ h, int n4)
{
    int i = blockIdx.x * blockDim.x + threadIdx.x;
    if (i >= n4) return;
    float4 v = ((const float4*)in)[i];
    ((f162*)h)[2 * i]     = __halves2half2(__float2half(v.x), __float2half(v.y));
    ((f162*)h)[2 * i + 1] = __halves2half2(__float2half(v.z), __float2half(v.w));
}

// in [z][R][C] fp32 -> out [z][C][R] f16 hi only
__global__ __launch_bounds__(256)
void transposeH(const float* __restrict__ in, f16* __restrict__ outh,
                int R, int C)
{
    __shared__ float t[32][33];
    const size_t zoff = (size_t)blockIdx.z * R * C;
    in += zoff; outh += zoff;
    const int c0 = blockIdx.x * 32, r0 = blockIdx.y * 32;
    const int tx = threadIdx.x;
    for (int i = threadIdx.y; i < 32; i += 8)
        t[i][tx] = in[(size_t)(r0 + i) * C + c0 + tx];
    __syncthreads();
    for (int i = threadIdx.y; i < 32; i += 8)
        outh[(size_t)(c0 + i) * R + r0 + tx] = __float2half(t[tx][i]);
}

// f16 single-plane transpose: in [R][C] -> out [C][R]
__global__ __launch_bounds__(256)
void transpose1(const f16* __restrict__ in, f16* __restrict__ out, int R, int C)
{
    __shared__ f16 t[32][33];
    const int c0 = blockIdx.x * 32, r0 = blockIdx.y * 32;
    const int tx = threadIdx.x;
    for (int i = threadIdx.y; i < 32; i += 8)
        t[i][tx] = in[(size_t)(r0 + i) * C + c0 + tx];
    __syncthreads();
    for (int i = threadIdx.y; i < 32; i += 8)
        out[(size_t)(c0 + i) * R + r0 + tx] = t[tx][i];
}

// ---------------- split-fp16 NT GEMM (cp.async pipelined) ----------------
// C[M,N] = A @ B^T, fp32 acc, 3-stage cp.async pipeline, CTA 128x128, BK=32.
// NPASS=2: A=(Ah+Al), B=Bh; passes AhBh + AlBh; 3 tiles/stage.
// NPASS=1: A=Ah, B=Bh; single pass; 2 tiles/stage.
// OMODE: 0 = fp32 C, 1 = hi/lo f16 C, 2 = hi-only f16 C.
// mode: 0 = plain, 1 = causal tile skip, 2 = K-cap at (blockIdx.y+1)*128.
// Mainloop: ALL ldsm for both k16 steps issued up-front (frag double-buffer)
// so the 128/256-mma block streams with a single latency exposure per iter.
#define LDSP 40                    // padded row in f16 elems (80B)
#define ROWB (LDSP * 2)            // 80
#define TILEB (128 * ROWB)         // 10240

template <int OMODE, int NPASS>
__global__ __launch_bounds__(128, 2)
void gemm2(const f16* __restrict__ Ah, const f16* __restrict__ Al,
           int lda, long long sA,
           const f16* __restrict__ Bh,
           int ldb, long long sB,
           void* __restrict__ Cp0, void* __restrict__ Cp1,
           int ldc, long long sC, int K, int mode)
{
    if (mode == 1 && blockIdx.x > blockIdx.y) return;

    constexpr int NTILES = (NPASS == 2) ? 3 : 2;
    constexpr int STAGES = 3;
    constexpr int STAGEB = NTILES * TILEB;
    constexpr uint32_t O_AH = 0;
    constexpr uint32_t O_AL = TILEB;                       // only if NPASS==2
    constexpr uint32_t O_BH = (NPASS == 2) ? 2 * TILEB : TILEB;

    extern __shared__ char smem[];
    const uint32_t sbase = smem_u32(smem);
    const int tid = threadIdx.x;
    const int lane = tid & 31;
    const int wid = tid >> 5;
    const int wm = (wid >> 1) * 64;
    const int wn = (wid & 1) * 64;

    Ah += (long long)blockIdx.z * sA;
    if (NPASS == 2) Al += (long long)blockIdx.z * sA;
    Bh += (long long)blockIdx.z * sB;
    const int m0 = blockIdx.y * 128;
    const int n0 = blockIdx.x * 128;

    const int row = tid >> 2;
    const int ch = tid & 3;

    auto issue = [&](int g) {
        const int k0 = g << 5;
        const uint32_t sb = sbase + (g % STAGES) * STAGEB;
        #pragma unroll
        for (int i = 0; i < 4; ++i) {
            int r = row + i * 32;
            uint32_t doff = (uint32_t)(r * ROWB + ch * 16);
            cp16(sb + O_AH + doff, Ah + (size_t)(m0 + r) * lda + k0 + ch * 8);
            if (NPASS == 2)
                cp16(sb + O_AL + doff, Al + (size_t)(m0 + r) * lda + k0 + ch * 8);
            cp16(sb + O_BH + doff, Bh + (size_t)(n0 + r) * ldb + k0 + ch * 8);
        }
        cp_commit();
    };

    float acc[4][8][4] = {};
    int nIter = K >> 5;
    if (mode == 2) {
        int kc = (int)(blockIdx.y + 1) << 7;
        if (kc < K) nIter = kc >> 5;
    }

    #pragma unroll
    for (int s = 0; s < STAGES - 1; ++s)
        if (s < nIter) issue(s);

    for (int it = 0; it < nIter; ++it) {
        if (it < nIter - 1) cp_wait<1>();
        else cp_wait<0>();
        __syncthreads();

        const uint32_t sb = sbase + (it % STAGES) * STAGEB;

        // ---- load ALL fragments for both k16 steps up front ----
        uint32_t Ahf[2][4][4], Alf[2][4][4], Bhf[2][8][2];
        #pragma unroll
        for (int s = 0; s < 2; ++s) {
            const int kk = s * 16;
            const uint32_t abase =
                (uint32_t)(((wm + (lane & 15)) * LDSP + kk + ((lane >> 4) << 3)) * 2);
            #pragma unroll
            for (int mi = 0; mi < 4; ++mi) {
                ldsm_x4(Ahf[s][mi][0], Ahf[s][mi][1], Ahf[s][mi][2], Ahf[s][mi][3],
                        sb + O_AH + abase + (uint32_t)(mi * 16 * ROWB));
                if (NPASS == 2)
                    ldsm_x4(Alf[s][mi][0], Alf[s][mi][1], Alf[s][mi][2], Alf[s][mi][3],
                            sb + O_AL + abase + (uint32_t)(mi * 16 * ROWB));
            }
            const uint32_t bbase =
                (uint32_t)(((wn + ((lane >> 4) << 3) + (lane & 7)) * LDSP +
                            kk + (((lane >> 3) & 1) << 3)) * 2);
            #pragma unroll
            for (int nt = 0; nt < 4; ++nt) {
                ldsm_x4(Bhf[s][2 * nt][0], Bhf[s][2 * nt][1],
                        Bhf[s][2 * nt + 1][0], Bhf[s][2 * nt + 1][1],
                        sb + O_BH + bbase + (uint32_t)(nt * 16 * ROWB));
            }
        }

        // ---- stream all mma ----
        #pragma unroll
        for (int s = 0; s < 2; ++s) {
            #pragma unroll
            for (int mi = 0; mi < 4; ++mi)
                #pragma unroll
                for (int ni = 0; ni < 8; ++ni)
                    mma_f16(acc[mi][ni][0], acc[mi][ni][1], acc[mi][ni][2], acc[mi][ni][3],
                            Ahf[s][mi][0], Ahf[s][mi][1], Ahf[s][mi][2], Ahf[s][mi][3],
                            Bhf[s][ni][0], Bhf[s][ni][1]);
            if (NPASS == 2) {
                #pragma unroll
                for (int mi = 0; mi < 4; ++mi)
                    #pragma unroll
                    for (int ni = 0; ni < 8; ++ni)
                        mma_f16(acc[mi][ni][0], acc[mi][ni][1], acc[mi][ni][2], acc[mi][ni][3],
                                Alf[s][mi][0], Alf[s][mi][1], Alf[s][mi][2], Alf[s][mi][3],
                                Bhf[s][ni][0], Bhf[s][ni][1]);
            }
        }
        if (it + 2 < nIter) issue(it + 2);
    }

    // ---- epilogue ----
    if (OMODE == 0) {
        float* C = (float*)Cp0 + (long long)blockIdx.z * sC;
        #pragma unroll
        for (int mi = 0; mi < 4; ++mi) {
            #pragma unroll
            for (int ni = 0; ni < 8; ++ni) {
                int r = m0 + wm + mi * 16 + (lane >> 2);
                int c = n0 + wn + ni * 8 + (lane & 3) * 2;
                *(float2*)&C[(size_t)r * ldc + c] =
                    make_float2(acc[mi][ni][0], acc[mi][ni][1]);
                *(float2*)&C[(size_t)(r + 8) * ldc + c] =
                    make_float2(acc[mi][ni][2], acc[mi][ni][3]);
            }
        }
    } else {
        f16* Ch = (f16*)Cp0 + (long long)blockIdx.z * sC;
        f16* Cl = (OMODE == 1) ? (f16*)Cp1 + (long long)blockIdx.z * sC : nullptr;
        #pragma unroll
        for (int mi = 0; mi < 4; ++mi) {
            #pragma unroll
            for (int ni = 0; ni < 8; ++ni) {
                int r = m0 + wm + mi * 16 + (lane >> 2);
                int c = n0 + wn + ni * 8 + (lane & 3) * 2;
                #pragma unroll
                for (int half = 0; half < 2; ++half) {
                    float a0 = acc[mi][ni][2 * half], a1 = acc[mi][ni][2 * half + 1];
                    f16 h0 = __float2half(a0), h1 = __float2half(a1);
                    size_t off = (size_t)(r + half * 8) * ldc + c;
                    *(f162*)&Ch[off] = __halves2half2(h0, h1);
                    if (OMODE == 1)
                        *(f162*)&Cl[off] = __halves2half2(
                            __float2half(a0 - __half2float(h0)),
                            __float2half(a1 - __half2float(h1)));
                }
            }
        }
    }
}

// ---------------- masked softmax (reads hi/lo logits, writes hi probs) -----
__global__ __launch_bounds__(256)
void softmax2(f16* __restrict__ Sh, f16* __restrict__ Sl)
{
    const int t = blockIdx.x;
    const int h = blockIdx.y;
    f162* rowh = (f162*)(Sh + ((size_t)h * TT + t) * TT);
    f162* rowl = (f162*)(Sl + ((size_t)h * TT + t) * TT);

    const float inv = 0.044194173824159216f; // 1/sqrt(512)
    const int tid = threadIdx.x;
    const int boundp = (((t >> 7) + 1) << 7) >> 1;  // pairs

    __shared__ float red[256];

    float vals[8];
    float lmax = -INFINITY;
    #pragma unroll
    for (int i = 0; i < 4; ++i) {
        int sp = tid + i * 256;
        if (sp >= boundp) break;
        int s = sp * 2;
        float2 vh = __half22float2(rowh[sp]);
        float2 vl = __half22float2(rowl[sp]);
        float v0 = -INFINITY, v1 = -INFINITY;
        if (s <= t) {
            v0 = (vh.x + vl.x) * inv;
            if (t - s < RA_WIN) v0 *= 1.5f;
            lmax = fmaxf(lmax, v0);
        }
        if (s + 1 <= t) {
            v1 = (vh.y + vl.y) * inv;
            if (t - (s + 1) < RA_WIN) v1 *= 1.5f;
            lmax = fmaxf(lmax, v1);
        }
        vals[2 * i] = v0;
        vals[2 * i + 1] = v1;
    }
    red[tid] = lmax;
    __syncthreads();
    #pragma unroll
    for (int o = 128; o > 0; o >>= 1) {
        if (tid < o) red[tid] = fmaxf(red[tid], red[tid + o]);
        __syncthreads();
    }
    const float m = red[0];
    __syncthreads();

    float lsum = 0.f;
    #pragma unroll
    for (int i = 0; i < 4; ++i) {
        int sp = tid + i * 256;
        if (sp >= boundp) break;
        int s = sp * 2;
        float e0 = 0.f, e1 = 0.f;
        if (s <= t)     { e0 = __expf(vals[2 * i] - m);     lsum += e0; }
        if (s + 1 <= t) { e1 = __expf(vals[2 * i + 1] - m); lsum += e1; }
        vals[2 * i] = e0;
        vals[2 * i + 1] = e1;
    }
    red[tid] = lsum;
    __syncthreads();
    #pragma unroll
    for (int o = 128; o > 0; o >>= 1) {
        if (tid < o) red[tid] += red[tid + o];
        __syncthreads();
    }
    const float inv_sum = 1.0f / red[0];

    #pragma unroll
    for (int i = 0; i < 4; ++i) {
        int sp = tid + i * 256;
        if (sp >= boundp) break;
        rowh[sp] = __halves2half2(
            __float2half(vals[2 * i] * inv_sum),
            __float2half(vals[2 * i + 1] * inv_sum));
    }
}

// ---------------- launch ----------------
extern "C" void kernel_launch(void* const* d_in, const int* in_sizes, int n_in,
                              void* d_out, int out_size)
{
    const float* hidden = (const float*)d_in[0]; // [T, E]
    const float* w_q    = (const float*)d_in[1]; // [E, E]
    const float* w_kd   = (const float*)d_in[2]; // [L, E]
    const float* w_vd   = (const float*)d_in[3]; // [L, E]
    const float* q2l    = (const float*)d_in[4]; // [H, D, L]
    const float* v_up   = (const float*)d_in[5]; // [H, L, D]
    const float* w_out  = (const float*)d_in[6]; // [E, E]
    float* out = (float*)d_out;                  // [T, E]

    f16 *hidh, *hidl, *wqh, *wkdh, *wvdh, *wouth, *q2lTh, *vupTh;
    f16 *Qh, *Ql, *latkh, *latvh, *latvl, *qlath, *qlatl;
    f16 *Vh, *VTh, *Sh, *Sl, *ctxh;
    cudaGetSymbolAddress((void**)&hidh, g_hidh);   cudaGetSymbolAddress((void**)&hidl, g_hidl);
    cudaGetSymbolAddress((void**)&wqh, g_wqh);
    cudaGetSymbolAddress((void**)&wkdh, g_wkdh);
    cudaGetSymbolAddress((void**)&wvdh, g_wvdh);
    cudaGetSymbolAddress((void**)&wouth, g_wouth);
    cudaGetSymbolAddress((void**)&q2lTh, g_q2lTh);
    cudaGetSymbolAddress((void**)&vupTh, g_vupTh);
    cudaGetSymbolAddress((void**)&Qh, g_Qh);       cudaGetSymbolAddress((void**)&Ql, g_Ql);
    cudaGetSymbolAddress((void**)&latkh, g_latkh);
    cudaGetSymbolAddress((void**)&latvh, g_latvh); cudaGetSymbolAddress((void**)&latvl, g_latvl);
    cudaGetSymbolAddress((void**)&qlath, g_qlath); cudaGetSymbolAddress((void**)&qlatl, g_qlatl);
    cudaGetSymbolAddress((void**)&Vh, g_Vh);
    cudaGetSymbolAddress((void**)&VTh, g_VTh);
    cudaGetSymbolAddress((void**)&Sh, g_Sh);       cudaGetSymbolAddress((void**)&Sl, g_Sl);
    cudaGetSymbolAddress((void**)&ctxh, g_ctxh);

    const int SM2 = 3 * 3 * TILEB;   // 2-pass: 3 stages x 3 tiles = 92160
    const int SM1 = 3 * 2 * TILEB;   // 1-pass: 3 stages x 2 tiles = 61440
    cudaFuncSetAttribute(gemm2<1, 2>, cudaFuncAttributeMaxDynamicSharedMemorySize, SM2);
    cudaFuncSetAttribute(gemm2<2, 2>, cudaFuncAttributeMaxDynamicSharedMemorySize, SM2);
    cudaFuncSetAttribute(gemm2<2, 1>, cudaFuncAttributeMaxDynamicSharedMemorySize, SM1);
    cudaFuncSetAttribute(gemm2<0, 1>, cudaFuncAttributeMaxDynamicSharedMemorySize, SM1);

    // ---- conversions ----
    split_k<<<(TT * EE / 4 + 255) / 256, 256>>>(hidden, hidh, hidl, TT * EE / 4);
    split_k1<<<(EE * EE / 4 + 255) / 256, 256>>>(w_q, wqh, EE * EE / 4);
    split_k1<<<(LL * EE / 4 + 255) / 256, 256>>>(w_kd, wkdh, LL * EE / 4);
    split_k1<<<(LL * EE / 4 + 255) / 256, 256>>>(w_vd, wvdh, LL * EE / 4);
    split_k1<<<(EE * EE / 4 + 255) / 256, 256>>>(w_out, wouth, EE * EE / 4);
    transposeH<<<dim3(LL / 32, DD / 32, HH), dim3(32, 8)>>>(q2l, q2lTh, DD, LL);
    transposeH<<<dim3(DD / 32, LL / 32, HH), dim3(32, 8)>>>(v_up, vupTh, LL, DD);

    dim3 blk(128);

    // 1) Q = hidden @ w_q^T  [2048,2048,2048]  (2-pass, hi/lo out)
    gemm2<1, 2><<<dim3(EE / 128, TT / 128, 1), blk, SM2>>>(
        hidh, hidl, EE, 0, wqh, EE, 0, Qh, Ql, EE, 0, EE, 0);

    // 2) latent_k = hidden @ w_k_down^T  [2048,512,2048]  (2-pass, hi-only out)
    gemm2<2, 2><<<dim3(LL / 128, TT / 128, 1), blk, SM2>>>(
        hidh, hidl, EE, 0, wkdh, EE, 0, latkh, nullptr, LL, 0, EE, 0);

    // 3) latent_v = hidden @ w_v_down^T  (2-pass, hi/lo out)
    gemm2<1, 2><<<dim3(LL / 128, TT / 128, 1), blk, SM2>>>(
        hidh, hidl, EE, 0, wvdh, EE, 0, latvh, latvl, LL, 0, EE, 0);

    // 4) q_latent[h] = Q[:,hD:] @ q2lT[h]^T  [2048,512,128]  (2-pass, hi/lo)
    gemm2<1, 2><<<dim3(LL / 128, TT / 128, HH), blk, SM2>>>(
        Qh, Ql, EE, DD, q2lTh, DD, (long long)LL * DD,
        qlath, qlatl, LL, (long long)TT * LL, DD, 0);

    // 5) V[:,h] = latent_v @ vupT[h]^T  [2048,128,512]  (2-pass, hi-only out)
    gemm2<2, 2><<<dim3(DD / 128, TT / 128, HH), blk, SM2>>>(
        latvh, latvl, LL, 0, vupTh, LL, (long long)DD * LL,
        Vh, nullptr, EE, DD, LL, 0);

    // 6) S[h] = q_latent[h] @ latent_k^T  [2048,2048,512]
    //    causal tile skip, 2-pass, hi/lo logits out
    gemm2<1, 2><<<dim3(TT / 128, TT / 128, HH), blk, SM2>>>(
        qlath, qlatl, LL, (long long)TT * LL, latkh, LL, 0,
        Sh, Sl, TT, (long long)TT * TT, LL, 1);

    // 7) V^T: [T][E] -> [E][T]  (hi only)
    transpose1<<<dim3(EE / 32, TT / 32), dim3(32, 8)>>>(Vh, VTh, TT, EE);

    // 8) masked softmax: read hi/lo logits, write hi probs, causal-bounded
    softmax2<<<dim3(TT, HH), dim3(256)>>>(Sh, Sl);

    // 9) ctx[:,h] = attn[h] @ VT[h]^T  [2048,128,2048]
    //    K-cap per row tile, 1-pass, hi-only ctx out
    gemm2<2, 1><<<dim3(DD / 128, TT / 128, HH), blk, SM1>>>(
        Sh, nullptr, TT, (long long)TT * TT, VTh, TT, (long long)DD * TT,
        ctxh, nullptr, EE, DD, TT, 2);

    // 10) out = ctx @ w_out^T  [2048,2048,2048]  (1-pass, fp32 out)
    gemm2<0, 1><<<dim3(EE / 128, TT / 128, 1), blk, SM1>>>(
        ctxh, nullptr, EE, 0, wouth, EE, 0, out, nullptr, EE, 0, EE, 0);
}

// round 13
// speedup vs baseline: 1.0243x; 1.0243x over previous
#include <cuda_runtime.h>
#include <cuda_fp16.h>
#include <math.h>
#include <stdint.h>

// Problem dims (fixed by the reference)
#define TT 2048   // tokens
#define EE 2048   // embed
#define HH 16     // heads
#define LL 512    // latent
#define DD 128    // head dim
#define RA_WIN 64

typedef __half f16;
typedef __half2 f162;

// ---------------- scratch (allocation-free: device globals) ----------------
__device__ f16 g_hidh[TT * EE],  g_hidl[TT * EE];
__device__ f16 g_wqh[EE * EE];
__device__ f16 g_wkdh[LL * EE];
__device__ f16 g_wvdh[LL * EE];
__device__ f16 g_wouth[EE * EE];
__device__ f16 g_q2lTh[HH * LL * DD];          // [H][L][D]
__device__ f16 g_vupTh[HH * DD * LL];          // [H][D][L]
__device__ f16 g_Qh[TT * EE],   g_Ql[TT * EE];
__device__ f16 g_latkh[TT * LL], g_latkl[TT * LL];   // latkl = dummy lo sink
__device__ f16 g_latvh[TT * LL], g_latvl[TT * LL];
__device__ f16 g_qlath[(size_t)HH * TT * LL], g_qlatl[(size_t)HH * TT * LL];
__device__ f16 g_Vh[TT * EE];                  // [T][H*D]
__device__ f16 g_VTh[EE * TT];                 // [H*D][T]
__device__ f16 g_Sh[(size_t)HH * TT * TT], g_Sl[(size_t)HH * TT * TT];
__device__ f16 g_ctxh[TT * EE];

// ---------------- helpers ----------------
__device__ __forceinline__ uint32_t smem_u32(const void* p) {
    uint32_t a;
    asm("{ .reg .u64 t; cvta.to.shared.u64 t, %1; cvt.u32.u64 %0, t; }"
        : "=r"(a) : "l"(p));
    return a;
}

__device__ __forceinline__ void cp16(uint32_t dst, const void* src) {
    asm volatile("cp.async.cg.shared.global [%0], [%1], 16;" :: "r"(dst), "l"(src));
}
__device__ __forceinline__ void cp_commit() {
    asm volatile("cp.async.commit_group;" ::: "memory");
}
template <int N>
__device__ __forceinline__ void cp_wait() {
    asm volatile("cp.async.wait_group %0;" :: "n"(N) : "memory");
}

__device__ __forceinline__ void ldsm_x4(uint32_t& r0, uint32_t& r1,
                                        uint32_t& r2, uint32_t& r3,
                                        uint32_t addr) {
    asm volatile("ldmatrix.sync.aligned.m8n8.x4.shared.b16 {%0,%1,%2,%3}, [%4];\n"
                 : "=r"(r0), "=r"(r1), "=r"(r2), "=r"(r3)
                 : "r"(addr));
}

__device__ __forceinline__ void mma_f16(float& c0, float& c1, float& c2, float& c3,
                                        uint32_t a0, uint32_t a1, uint32_t a2, uint32_t a3,
                                        uint32_t b0, uint32_t b1) {
    asm volatile("mma.sync.aligned.m16n8k16.row.col.f32.f16.f16.f32 "
                 "{%0,%1,%2,%3}, {%4,%5,%6,%7}, {%8,%9}, {%0,%1,%2,%3};\n"
                 : "+f"(c0), "+f"(c1), "+f"(c2), "+f"(c3)
                 : "r"(a0), "r"(a1), "r"(a2), "r"(a3), "r"(b0), "r"(b1));
}

// ---------------- conversion kernels ----------------
__global__ __launch_bounds__(256)
void split_k(const float* __restrict__ in, f16* __restrict__ h,
             f16* __restrict__ l, int n4)
{
    int i = blockIdx.x * blockDim.x + threadIdx.x;
    if (i >= n4) return;
    float4 v = ((const float4*)in)[i];
    f16 hx = __float2half(v.x), hy = __float2half(v.y);
    f16 hz = __float2half(v.z), hw = __float2half(v.w);
    ((f162*)h)[2 * i]     = __halves2half2(hx, hy);
    ((f162*)h)[2 * i + 1] = __halves2half2(hz, hw);
    ((f162*)l)[2 * i] = __halves2half2(
        __float2half(v.x - __half2float(hx)),
        __float2half(v.y - __half2float(hy)));
    ((f162*)l)[2 * i + 1] = __halves2half2(
        __float2half(v.z - __half2float(hz)),
        __float2half(v.w - __half2float(hw)));
}

__global__ __launch_bounds__(256)
void split_k1(const float* __restrict__ in, f16* __restrict__ h, int n4)
{
    int i = blockIdx.x * blockDim.x + threadIdx.x;
    if (i >= n4) return;
    float4 v = ((const float4*)in)[i];
    ((f162*)h)[2 * i]     = __halves2half2(__float2half(v.x), __float2half(v.y));
    ((f162*)h)[2 * i + 1] = __halves2half2(__float2half(v.z), __float2half(v.w));
}

// in [z][R][C] fp32 -> out [z][C][R] f16 hi only
__global__ __launch_bounds__(256)
void transposeH(const float* __restrict__ in, f16* __restrict__ outh,
                int R, int C)
{
    __shared__ float t[32][33];
    const size_t zoff = (size_t)blockIdx.z * R * C;
    in += zoff; outh += zoff;
    const int c0 = blockIdx.x * 32, r0 = blockIdx.y * 32;
    const int tx = threadIdx.x;
    for (int i = threadIdx.y; i < 32; i += 8)
        t[i][tx] = in[(size_t)(r0 + i) * C + c0 + tx];
    __syncthreads();
    for (int i = threadIdx.y; i < 32; i += 8)
        outh[(size_t)(c0 + i) * R + r0 + tx] = __float2half(t[tx][i]);
}

// f16 single-plane transpose: in [R][C] -> out [C][R]
__global__ __launch_bounds__(256)
void transpose1(const f16* __restrict__ in, f16* __restrict__ out, int R, int C)
{
    __shared__ f16 t[32][33];
    const int c0 = blockIdx.x * 32, r0 = blockIdx.y * 32;
    const int tx = threadIdx.x;
    for (int i = threadIdx.y; i < 32; i += 8)
        t[i][tx] = in[(size_t)(r0 + i) * C + c0 + tx];
    __syncthreads();
    for (int i = threadIdx.y; i < 32; i += 8)
        out[(size_t)(c0 + i) * R + r0 + tx] = t[tx][i];
}

// ---------------- split-fp16 NT GEMM (cp.async pipelined) ----------------
// C[M,N] = A @ B^T, fp32 acc, 3-stage cp.async pipeline, CTA (MW*64)x128, BK=32.
// MW = m-warps: MW=2 -> 128x128 CTA (4 warps, 2 CTAs/SM);
//               MW=4 -> 256x128 CTA (8 warps, 1 CTA/SM; better smem/mma ratio).
// NPASS=2: A=(Ah+Al), B=Bh; passes AhBh + AlBh.
// NPASS=1: A=Ah, B=Bh; single pass.
// OMODE: 0 = fp32 C, 1 = hi/lo f16 C, 2 = hi-only f16 C.
// mode: 0 = plain, 1 = causal tile skip, 2 = K-cap at (blockIdx.y+1)*MROWS.
// BhAlt/CAlt: when non-null and blockIdx.z==1, swap B/C pointers (fused dual GEMM).
#define LDSP 40                    // padded row in f16 elems (80B)
#define ROWB (LDSP * 2)            // 80
#define BTILEB (128 * ROWB)        // 10240

template <int OMODE, int NPASS, int MW>
__global__ __launch_bounds__(MW * 64, 4 / MW)
void gemm2(const f16* __restrict__ Ah, const f16* __restrict__ Al,
           int lda, long long sA,
           const f16* __restrict__ Bh,
           int ldb, long long sB,
           void* __restrict__ Cp0, void* __restrict__ Cp1,
           int ldc, long long sC, int K, int mode,
           const f16* __restrict__ BhAlt,
           void* __restrict__ CAlt0, void* __restrict__ CAlt1)
{
    constexpr int MROWS = MW * 64;
    if (mode == 1 && (int)(blockIdx.x * 128) >= (int)((blockIdx.y + 1) * MROWS)) return;

    constexpr int ATILEB = MROWS * ROWB;
    constexpr int STAGES = 3;
    constexpr int STAGEB = ((NPASS == 2) ? 2 : 1) * ATILEB + BTILEB;
    constexpr uint32_t O_AH = 0;
    constexpr uint32_t O_AL = ATILEB;                      // only if NPASS==2
    constexpr uint32_t O_BH = ((NPASS == 2) ? 2 : 1) * ATILEB;

    extern __shared__ char smem[];
    const uint32_t sbase = smem_u32(smem);
    const int tid = threadIdx.x;
    const int lane = tid & 31;
    const int wid = tid >> 5;
    const int wm = (wid >> 1) * 64;
    const int wn = (wid & 1) * 64;

    if (BhAlt && blockIdx.z) {
        Bh = BhAlt; Cp0 = CAlt0; Cp1 = CAlt1;
    }
    Ah += (long long)blockIdx.z * sA;
    if (NPASS == 2) Al += (long long)blockIdx.z * sA;
    Bh += (long long)blockIdx.z * sB;
    const int m0 = blockIdx.y * MROWS;
    const int n0 = blockIdx.x * 128;

    const int row = tid >> 2;      // 0 .. MW*16-1
    const int ch = tid & 3;

    auto issue = [&](int g) {
        const int k0 = g << 5;
        const uint32_t sb = sbase + (g % STAGES) * STAGEB;
        #pragma unroll
        for (int i = 0; i < 4; ++i) {                      // A: MROWS rows
            int r = row + i * (MW * 16);
            uint32_t doff = (uint32_t)(r * ROWB + ch * 16);
            cp16(sb + O_AH + doff, Ah + (size_t)(m0 + r) * lda + k0 + ch * 8);
            if (NPASS == 2)
                cp16(sb + O_AL + doff, Al + (size_t)(m0 + r) * lda + k0 + ch * 8);
        }
        #pragma unroll
        for (int i = 0; i < 8 / MW; ++i) {                 // B: 128 rows
            int r = row + i * (MW * 16);
            uint32_t doff = (uint32_t)(r * ROWB + ch * 16);
            cp16(sb + O_BH + doff, Bh + (size_t)(n0 + r) * ldb + k0 + ch * 8);
        }
        cp_commit();
    };

    float acc[4][8][4] = {};
    int nIter = K >> 5;
    if (mode == 2) {
        int kc = (int)(blockIdx.y + 1) * MROWS;
        if (kc < K) nIter = kc >> 5;
    }

    #pragma unroll
    for (int s = 0; s < STAGES - 1; ++s)
        if (s < nIter) issue(s);

    for (int it = 0; it < nIter; ++it) {
        if (it < nIter - 1) cp_wait<1>();
        else cp_wait<0>();
        __syncthreads();

        const uint32_t sb = sbase + (it % STAGES) * STAGEB;
        #pragma unroll
        for (int kk = 0; kk < 32; kk += 16) {
            uint32_t Ahf[4][4], Alf[4][4], Bhf[8][2];

            const uint32_t abase =
                (uint32_t)(((wm + (lane & 15)) * LDSP + kk + ((lane >> 4) << 3)) * 2);
            #pragma unroll
            for (int mi = 0; mi < 4; ++mi) {
                ldsm_x4(Ahf[mi][0], Ahf[mi][1], Ahf[mi][2], Ahf[mi][3],
                        sb + O_AH + abase + (uint32_t)(mi * 16 * ROWB));
                if (NPASS == 2)
                    ldsm_x4(Alf[mi][0], Alf[mi][1], Alf[mi][2], Alf[mi][3],
                            sb + O_AL + abase + (uint32_t)(mi * 16 * ROWB));
            }
            const uint32_t bbase =
                (uint32_t)(((wn + ((lane >> 4) << 3) + (lane & 7)) * LDSP +
                            kk + (((lane >> 3) & 1) << 3)) * 2);
            #pragma unroll
            for (int nt = 0; nt < 4; ++nt) {
                ldsm_x4(Bhf[2 * nt][0], Bhf[2 * nt][1],
                        Bhf[2 * nt + 1][0], Bhf[2 * nt + 1][1],
                        sb + O_BH + bbase + (uint32_t)(nt * 16 * ROWB));
            }

            #pragma unroll
            for (int mi = 0; mi < 4; ++mi)
                #pragma unroll
                for (int ni = 0; ni < 8; ++ni)
                    mma_f16(acc[mi][ni][0], acc[mi][ni][1], acc[mi][ni][2], acc[mi][ni][3],
                            Ahf[mi][0], Ahf[mi][1], Ahf[mi][2], Ahf[mi][3],
                            Bhf[ni][0], Bhf[ni][1]);
            if (NPASS == 2) {
                #pragma unroll
                for (int mi = 0; mi < 4; ++mi)
                    #pragma unroll
                    for (int ni = 0; ni < 8; ++ni)
                        mma_f16(acc[mi][ni][0], acc[mi][ni][1], acc[mi][ni][2], acc[mi][ni][3],
                                Alf[mi][0], Alf[mi][1], Alf[mi][2], Alf[mi][3],
                                Bhf[ni][0], Bhf[ni][1]);
            }
        }
        if (it + 2 < nIter) issue(it + 2);
    }

    // ---- epilogue ----
    if (OMODE == 0) {
        float* C = (float*)Cp0 + (long long)blockIdx.z * sC;
        #pragma unroll
        for (int mi = 0; mi < 4; ++mi) {
            #pragma unroll
            for (int ni = 0; ni < 8; ++ni) {
                int r = m0 + wm + mi * 16 + (lane >> 2);
                int c = n0 + wn + ni * 8 + (lane & 3) * 2;
                *(float2*)&C[(size_t)r * ldc + c] =
                    make_float2(acc[mi][ni][0], acc[mi][ni][1]);
                *(float2*)&C[(size_t)(r + 8) * ldc + c] =
                    make_float2(acc[mi][ni][2], acc[mi][ni][3]);
            }
        }
    } else {
        f16* Ch = (f16*)Cp0 + (long long)blockIdx.z * sC;
        f16* Cl = (OMODE == 1) ? (f16*)Cp1 + (long long)blockIdx.z * sC : nullptr;
        #pragma unroll
        for (int mi = 0; mi < 4; ++mi) {
            #pragma unroll
            for (int ni = 0; ni < 8; ++ni) {
                int r = m0 + wm + mi * 16 + (lane >> 2);
                int c = n0 + wn + ni * 8 + (lane & 3) * 2;
                #pragma unroll
                for (int half = 0; half < 2; ++half) {
                    float a0 = acc[mi][ni][2 * half], a1 = acc[mi][ni][2 * half + 1];
                    f16 h0 = __float2half(a0), h1 = __float2half(a1);
                    size_t off = (size_t)(r + half * 8) * ldc + c;
                    *(f162*)&Ch[off] = __halves2half2(h0, h1);
                    if (OMODE == 1)
                        *(f162*)&Cl[off] = __halves2half2(
                            __float2half(a0 - __half2float(h0)),
                            __float2half(a1 - __half2float(h1)));
                }
            }
        }
    }
}

// ---------------- masked softmax (reads hi/lo logits, writes hi probs) -----
// Zero-fills probs out to a 256-aligned bound so the MW=4 attn*V K-cap
// (which reads in 256-row granules) never sees raw logits.
__global__ __launch_bounds__(256)
void softmax2(f16* __restrict__ Sh, f16* __restrict__ Sl)
{
    const int t = blockIdx.x;
    const int h = blockIdx.y;
    f162* rowh = (f162*)(Sh + ((size_t)h * TT + t) * TT);
    f162* rowl = (f162*)(Sl + ((size_t)h * TT + t) * TT);

    const float inv = 0.044194173824159216f; // 1/sqrt(512)
    const int tid = threadIdx.x;
    const int boundp = (((t >> 8) + 1) << 8) >> 1;  // 256-aligned, in pairs

    __shared__ float red[256];

    float vals[8];
    float lmax = -INFINITY;
    #pragma unroll
    for (int i = 0; i < 4; ++i) {
        int sp = tid + i * 256;
        if (sp >= boundp) break;
        int s = sp * 2;
        float v0 = -INFINITY, v1 = -INFINITY;
        if (s <= t) {
            float2 vh = __half22float2(rowh[sp]);
            float2 vl = __half22float2(rowl[sp]);
            v0 = (vh.x + vl.x) * inv;
            if (t - s < RA_WIN) v0 *= 1.5f;
            lmax = fmaxf(lmax, v0);
            if (s + 1 <= t) {
                v1 = (vh.y + vl.y) * inv;
                if (t - (s + 1) < RA_WIN) v1 *= 1.5f;
                lmax = fmaxf(lmax, v1);
            }
        }
        vals[2 * i] = v0;
        vals[2 * i + 1] = v1;
    }
    red[tid] = lmax;
    __syncthreads();
    #pragma unroll
    for (int o = 128; o > 0; o >>= 1) {
        if (tid < o) red[tid] = fmaxf(red[tid], red[tid + o]);
        __syncthreads();
    }
    const float m = red[0];
    __syncthreads();

    float lsum = 0.f;
    #pragma unroll
    for (int i = 0; i < 4; ++i) {
        int sp = tid + i * 256;
        if (sp >= boundp) break;
        int s = sp * 2;
        float e0 = 0.f, e1 = 0.f;
        if (s <= t)     { e0 = __expf(vals[2 * i] - m);     lsum += e0; }
        if (s + 1 <= t) { e1 = __expf(vals[2 * i + 1] - m); lsum += e1; }
        vals[2 * i] = e0;
        vals[2 * i + 1] = e1;
    }
    red[tid] = lsum;
    __syncthreads();
    #pragma unroll
    for (int o = 128; o > 0; o >>= 1) {
        if (tid < o) red[tid] += red[tid + o];
        __syncthreads();
    }
    const float inv_sum = 1.0f / red[0];

    #pragma unroll
    for (int i = 0; i < 4; ++i) {
        int sp = tid + i * 256;
        if (sp >= boundp) break;
        rowh[sp] = __halves2half2(
            __float2half(vals[2 * i] * inv_sum),
            __float2half(vals[2 * i + 1] * inv_sum));
    }
}

// ---------------- launch ----------------
extern "C" void kernel_launch(void* const* d_in, const int* in_sizes, int n_in,
                              void* d_out, int out_size)
{
    const float* hidden = (const float*)d_in[0]; // [T, E]
    const float* w_q    = (const float*)d_in[1]; // [E, E]
    const float* w_kd   = (const float*)d_in[2]; // [L, E]
    const float* w_vd   = (const float*)d_in[3]; // [L, E]
    const float* q2l    = (const float*)d_in[4]; // [H, D, L]
    const float* v_up   = (const float*)d_in[5]; // [H, L, D]
    const float* w_out  = (const float*)d_in[6]; // [E, E]
    float* out = (float*)d_out;                  // [T, E]

    f16 *hidh, *hidl, *wqh, *wkdh, *wvdh, *wouth, *q2lTh, *vupTh;
    f16 *Qh, *Ql, *latkh, *latkl, *latvh, *latvl, *qlath, *qlatl;
    f16 *Vh, *VTh, *Sh, *Sl, *ctxh;
    cudaGetSymbolAddress((void**)&hidh, g_hidh);   cudaGetSymbolAddress((void**)&hidl, g_hidl);
    cudaGetSymbolAddress((void**)&wqh, g_wqh);
    cudaGetSymbolAddress((void**)&wkdh, g_wkdh);
    cudaGetSymbolAddress((void**)&wvdh, g_wvdh);
    cudaGetSymbolAddress((void**)&wouth, g_wouth);
    cudaGetSymbolAddress((void**)&q2lTh, g_q2lTh);
    cudaGetSymbolAddress((void**)&vupTh, g_vupTh);
    cudaGetSymbolAddress((void**)&Qh, g_Qh);       cudaGetSymbolAddress((void**)&Ql, g_Ql);
    cudaGetSymbolAddress((void**)&latkh, g_latkh); cudaGetSymbolAddress((void**)&latkl, g_latkl);
    cudaGetSymbolAddress((void**)&latvh, g_latvh); cudaGetSymbolAddress((void**)&latvl, g_latvl);
    cudaGetSymbolAddress((void**)&qlath, g_qlath); cudaGetSymbolAddress((void**)&qlatl, g_qlatl);
    cudaGetSymbolAddress((void**)&Vh, g_Vh);
    cudaGetSymbolAddress((void**)&VTh, g_VTh);
    cudaGetSymbolAddress((void**)&Sh, g_Sh);       cudaGetSymbolAddress((void**)&Sl, g_Sl);
    cudaGetSymbolAddress((void**)&ctxh, g_ctxh);

    // smem sizes: stage = npass_planes*MROWS*80 + 128*80, x3 stages
    const int SM_2_2 = 3 * (2 * 128 * ROWB + BTILEB);   // 92160
    const int SM_2_4 = 3 * (2 * 256 * ROWB + BTILEB);   // 153600
    const int SM_1_4 = 3 * (1 * 256 * ROWB + BTILEB);   // 92160
    cudaFuncSetAttribute(gemm2<1, 2, 2>, cudaFuncAttributeMaxDynamicSharedMemorySize, SM_2_2);
    cudaFuncSetAttribute(gemm2<2, 2, 2>, cudaFuncAttributeMaxDynamicSharedMemorySize, SM_2_2);
    cudaFuncSetAttribute(gemm2<1, 2, 4>, cudaFuncAttributeMaxDynamicSharedMemorySize, SM_2_4);
    cudaFuncSetAttribute(gemm2<2, 1, 4>, cudaFuncAttributeMaxDynamicSharedMemorySize, SM_1_4);
    cudaFuncSetAttribute(gemm2<0, 1, 4>, cudaFuncAttributeMaxDynamicSharedMemorySize, SM_1_4);

    // ---- conversions ----
    split_k<<<(TT * EE / 4 + 255) / 256, 256>>>(hidden, hidh, hidl, TT * EE / 4);
    split_k1<<<(EE * EE / 4 + 255) / 256, 256>>>(w_q, wqh, EE * EE / 4);
    split_k1<<<(LL * EE / 4 + 255) / 256, 256>>>(w_kd, wkdh, LL * EE / 4);
    split_k1<<<(LL * EE / 4 + 255) / 256, 256>>>(w_vd, wvdh, LL * EE / 4);
    split_k1<<<(EE * EE / 4 + 255) / 256, 256>>>(w_out, wouth, EE * EE / 4);
    transposeH<<<dim3(LL / 32, DD / 32, HH), dim3(32, 8)>>>(q2l, q2lTh, DD, LL);
    transposeH<<<dim3(DD / 32, LL / 32, HH), dim3(32, 8)>>>(v_up, vupTh, LL, DD);

    // 1) Q = hidden @ w_q^T  [2048,2048,2048]  (2-pass, hi/lo out, 256-tile)
    gemm2<1, 2, 4><<<dim3(EE / 128, TT / 256, 1), dim3(256), SM_2_4>>>(
        hidh, hidl, EE, 0, wqh, EE, 0, Qh, Ql, EE, 0, EE, 0,
        nullptr, nullptr, nullptr);

    // 2+3) latent_k / latent_v fused (z=0 -> latk, z=1 -> latv), 2-pass hi/lo
    //      (latk's lo plane goes to a dummy sink; only latkh is consumed)
    gemm2<1, 2, 2><<<dim3(LL / 128, TT / 128, 2), dim3(128), SM_2_2>>>(
        hidh, hidl, EE, 0, wkdh, EE, 0, latkh, latkl, LL, 0, EE, 0,
        wvdh, latvh, latvl);

    // 4) q_latent[h] = Q[:,hD:] @ q2lT[h]^T  [2048,512,128]  (2-pass, hi/lo)
    gemm2<1, 2, 2><<<dim3(LL / 128, TT / 128, HH), dim3(128), SM_2_2>>>(
        Qh, Ql, EE, DD, q2lTh, DD, (long long)LL * DD,
        qlath, qlatl, LL, (long long)TT * LL, DD, 0,
        nullptr, nullptr, nullptr);

    // 5) V[:,h] = latent_v @ vupT[h]^T  [2048,128,512]  (2-pass, hi-only out)
    gemm2<2, 2, 2><<<dim3(DD / 128, TT / 128, HH), dim3(128), SM_2_2>>>(
        latvh, latvl, LL, 0, vupTh, LL, (long long)DD * LL,
        Vh, nullptr, EE, DD, LL, 0,
        nullptr, nullptr, nullptr);

    // 6) S[h] = q_latent[h] @ latent_k^T  [2048,2048,512]
    //    causal tile skip, 2-pass, hi/lo logits out, 256-tile
    gemm2<1, 2, 4><<<dim3(TT / 128, TT / 256, HH), dim3(256), SM_2_4>>>(
        qlath, qlatl, LL, (long long)TT * LL, latkh, LL, 0,
        Sh, Sl, TT, (long long)TT * TT, LL, 1,
        nullptr, nullptr, nullptr);

    // 7) V^T: [T][E] -> [E][T]  (hi only)
    transpose1<<<dim3(EE / 32, TT / 32), dim3(32, 8)>>>(Vh, VTh, TT, EE);

    // 8) masked softmax: read hi/lo logits, write hi probs, 256-aligned bound
    softmax2<<<dim3(TT, HH), dim3(256)>>>(Sh, Sl);

    // 9) ctx[:,h] = attn[h] @ VT[h]^T  [2048,128,2048]
    //    K-cap per 256-row tile, 1-pass, hi-only ctx out, 256-tile
    gemm2<2, 1, 4><<<dim3(DD / 128, TT / 256, HH), dim3(256), SM_1_4>>>(
        Sh, nullptr, TT, (long long)TT * TT, VTh, TT, (long long)DD * TT,
        ctxh, nullptr, EE, DD, TT, 2,
        nullptr, nullptr, nullptr);

    // 10) out = ctx @ w_out^T  [2048,2048,2048]  (1-pass, fp32 out, 256-tile)
    gemm2<0, 1, 4><<<dim3(EE / 128, TT / 256, 1), dim3(256), SM_1_4>>>(
        ctxh, nullptr, EE, 0, wouth, EE, 0, out, nullptr, EE, 0, EE, 0,
        nullptr, nullptr, nullptr);
}

// round 15
// speedup vs baseline: 1.0367x; 1.0121x over previous
#include <cuda_runtime.h>
#include <cuda_fp16.h>
#include <math.h>
#include <stdint.h>

// Problem dims (fixed by the reference)
#define TT 2048   // tokens
#define EE 2048   // embed
#define HH 16     // heads
#define LL 512    // latent
#define DD 128    // head dim
#define RA_WIN 64

typedef __half f16;
typedef __half2 f162;

// ---------------- scratch (allocation-free: device globals) ----------------
__device__ f16 g_hidh[TT * EE],  g_hidl[TT * EE];
__device__ f16 g_wqh[EE * EE];
__device__ f16 g_wkdh[LL * EE];
__device__ f16 g_wvdh[LL * EE];
__device__ f16 g_wouth[EE * EE];
__device__ f16 g_q2lTh[HH * LL * DD];          // [H][L][D]
__device__ f16 g_vupTh[HH * DD * LL];          // [H][D][L]
__device__ f16 g_Qh[TT * EE],   g_Ql[TT * EE];
__device__ f16 g_latkh[TT * LL], g_latkl[TT * LL];   // latkl = dummy lo sink
__device__ f16 g_latvh[TT * LL], g_latvl[TT * LL];
__device__ f16 g_qlath[(size_t)HH * TT * LL], g_qlatl[(size_t)HH * TT * LL];
__device__ f16 g_Vh[TT * EE];                  // [T][H*D]
__device__ f16 g_VTh[EE * TT];                 // [H*D][T]
__device__ f16 g_Sh[(size_t)HH * TT * TT], g_Sl[(size_t)HH * TT * TT];
__device__ f16 g_ctxh[TT * EE];

// ---------------- helpers ----------------
__device__ __forceinline__ uint32_t smem_u32(const void* p) {
    uint32_t a;
    asm("{ .reg .u64 t; cvta.to.shared.u64 t, %1; cvt.u32.u64 %0, t; }"
        : "=r"(a) : "l"(p));
    return a;
}

__device__ __forceinline__ void cp16(uint32_t dst, const void* src) {
    asm volatile("cp.async.cg.shared.global [%0], [%1], 16;" :: "r"(dst), "l"(src));
}
__device__ __forceinline__ void cp_commit() {
    asm volatile("cp.async.commit_group;" ::: "memory");
}
template <int N>
__device__ __forceinline__ void cp_wait() {
    asm volatile("cp.async.wait_group %0;" :: "n"(N) : "memory");
}

__device__ __forceinline__ void ldsm_x4(uint32_t& r0, uint32_t& r1,
                                        uint32_t& r2, uint32_t& r3,
                                        uint32_t addr) {
    asm volatile("ldmatrix.sync.aligned.m8n8.x4.shared.b16 {%0,%1,%2,%3}, [%4];\n"
                 : "=r"(r0), "=r"(r1), "=r"(r2), "=r"(r3)
                 : "r"(addr));
}

__device__ __forceinline__ void mma_f16(float& c0, float& c1, float& c2, float& c3,
                                        uint32_t a0, uint32_t a1, uint32_t a2, uint32_t a3,
                                        uint32_t b0, uint32_t b1) {
    asm volatile("mma.sync.aligned.m16n8k16.row.col.f32.f16.f16.f32 "
                 "{%0,%1,%2,%3}, {%4,%5,%6,%7}, {%8,%9}, {%0,%1,%2,%3};\n"
                 : "+f"(c0), "+f"(c1), "+f"(c2), "+f"(c3)
                 : "r"(a0), "r"(a1), "r"(a2), "r"(a3), "r"(b0), "r"(b1));
}

// ---------------- conversion kernels ----------------
__global__ __launch_bounds__(256)
void split_k(const float* __restrict__ in, f16* __restrict__ h,
             f16* __restrict__ l, int n4)
{
    int i = blockIdx.x * blockDim.x + threadIdx.x;
    if (i >= n4) return;
    float4 v = ((const float4*)in)[i];
    f16 hx = __float2half(v.x), hy = __float2half(v.y);
    f16 hz = __float2half(v.z), hw = __float2half(v.w);
    ((f162*)h)[2 * i]     = __halves2half2(hx, hy);
    ((f162*)h)[2 * i + 1] = __halves2half2(hz, hw);
    ((f162*)l)[2 * i] = __halves2half2(
        __float2half(v.x - __half2float(hx)),
        __float2half(v.y - __half2float(hy)));
    ((f162*)l)[2 * i + 1] = __halves2half2(
        __float2half(v.z - __half2float(hz)),
        __float2half(v.w - __half2float(hw)));
}

__global__ __launch_bounds__(256)
void split_k1(const float* __restrict__ in, f16* __restrict__ h, int n4)
{
    int i = blockIdx.x * blockDim.x + threadIdx.x;
    if (i >= n4) return;
    float4 v = ((const float4*)in)[i];
    ((f162*)h)[2 * i]     = __halves2half2(__float2half(v.x), __float2half(v.y));
    ((f162*)h)[2 * i + 1] = __halves2half2(__float2half(v.z), __float2half(v.w));
}

// in [z][R][C] fp32 -> out [z][C][R] f16 hi only
__global__ __launch_bounds__(256)
void transposeH(const float* __restrict__ in, f16* __restrict__ outh,
                int R, int C)
{
    __shared__ float t[32][33];
    const size_t zoff = (size_t)blockIdx.z * R * C;
    in += zoff; outh += zoff;
    const int c0 = blockIdx.x * 32, r0 = blockIdx.y * 32;
    const int tx = threadIdx.x;
    for (int i = threadIdx.y; i < 32; i += 8)
        t[i][tx] = in[(size_t)(r0 + i) * C + c0 + tx];
    __syncthreads();
    for (int i = threadIdx.y; i < 32; i += 8)
        outh[(size_t)(c0 + i) * R + r0 + tx] = __float2half(t[tx][i]);
}

// f16 single-plane transpose: in [R][C] -> out [C][R]
__global__ __launch_bounds__(256)
void transpose1(const f16* __restrict__ in, f16* __restrict__ out, int R, int C)
{
    __shared__ f16 t[32][33];
    const int c0 = blockIdx.x * 32, r0 = blockIdx.y * 32;
    const int tx = threadIdx.x;
    for (int i = threadIdx.y; i < 32; i += 8)
        t[i][tx] = in[(size_t)(r0 + i) * C + c0 + tx];
    __syncthreads();
    for (int i = threadIdx.y; i < 32; i += 8)
        out[(size_t)(c0 + i) * R + r0 + tx] = t[tx][i];
}

// ---------------- split-fp16 NT GEMM (cp.async pipelined) ----------------
// C[M,N] = A @ B^T, fp32 acc, cp.async pipeline, CTA (MW*64)x128, BK=32.
// MW: 2 -> 128x128 CTA (4 warps, 2 CTAs/SM); 4 -> 256x128 (8 warps, 1 CTA/SM).
// NPASS=2: A=(Ah+Al), B=Bh, 2 passes, 3 stages. NPASS=1: single pass, 4 stages.
// OMODE: 0 = fp32 C, 1 = hi/lo f16 C, 2 = hi-only f16 C.
// mode: 0 plain; 1 causal tile skip; 2 K-cap at (y+1)*MROWS;
//       3 PAIR-BALANCED K-cap: CTA does m-tiles y and (2*gridDim.y-1-y).
// Tail wait is remaining-groups aware (fixes 4-stage under-wait race).
// BhAlt/CAlt: when non-null and blockIdx.z==1, swap B/C pointers (fused dual GEMM).
#define LDSP 40                    // padded row in f16 elems (80B)
#define ROWB (LDSP * 2)            // 80
#define BTILEB (128 * ROWB)        // 10240

template <int OMODE, int NPASS, int MW>
__global__ __launch_bounds__(MW * 64, 4 / MW)
void gemm2(const f16* __restrict__ Ah, const f16* __restrict__ Al,
           int lda, long long sA,
           const f16* __restrict__ Bh,
           int ldb, long long sB,
           void* __restrict__ Cp0, void* __restrict__ Cp1,
           int ldc, long long sC, int K, int mode,
           const f16* __restrict__ BhAlt,
           void* __restrict__ CAlt0, void* __restrict__ CAlt1)
{
    constexpr int MROWS = MW * 64;
    if (mode == 1 && (int)(blockIdx.x * 128) >= (int)((blockIdx.y + 1) * MROWS)) return;

    constexpr int ATILEB = MROWS * ROWB;
    constexpr int STAGES = (NPASS == 1) ? 4 : 3;
    constexpr int STAGEB = ((NPASS == 2) ? 2 : 1) * ATILEB + BTILEB;
    constexpr uint32_t O_AH = 0;
    constexpr uint32_t O_AL = ATILEB;                      // only if NPASS==2
    constexpr uint32_t O_BH = ((NPASS == 2) ? 2 : 1) * ATILEB;

    extern __shared__ char smem[];
    const uint32_t sbase = smem_u32(smem);
    const int tid = threadIdx.x;
    const int lane = tid & 31;
    const int wid = tid >> 5;
    const int wm = (wid >> 1) * 64;
    const int wn = (wid & 1) * 64;

    if (BhAlt && blockIdx.z) {
        Bh = BhAlt; Cp0 = CAlt0; Cp1 = CAlt1;
    }
    Ah += (long long)blockIdx.z * sA;
    if (NPASS == 2) Al += (long long)blockIdx.z * sA;
    Bh += (long long)blockIdx.z * sB;
    const int n0 = blockIdx.x * 128;

    const int row = tid >> 2;      // 0 .. MW*16-1
    const int ch = tid & 3;

    const int ntile = (mode == 3) ? 2 : 1;

    for (int ti = 0; ti < ntile; ++ti) {
        const int yb = (ti == 0) ? (int)blockIdx.y
                                 : (int)(2 * gridDim.y - 1 - blockIdx.y);
        const int m0 = yb * MROWS;

        int nIter = K >> 5;
        if (mode == 2 || mode == 3) {
            int kc = (yb + 1) * MROWS;
            if (kc < K) nIter = kc >> 5;
        }

        if (ti) __syncthreads();   // protect smem stages between tiles

        auto issue = [&](int g) {
            const int k0 = g << 5;
            const uint32_t sb = sbase + (g % STAGES) * STAGEB;
            #pragma unroll
            for (int i = 0; i < 4; ++i) {                      // A: MROWS rows
                int r = row + i * (MW * 16);
                uint32_t doff = (uint32_t)(r * ROWB + ch * 16);
                cp16(sb + O_AH + doff, Ah + (size_t)(m0 + r) * lda + k0 + ch * 8);
                if (NPASS == 2)
                    cp16(sb + O_AL + doff, Al + (size_t)(m0 + r) * lda + k0 + ch * 8);
            }
            #pragma unroll
            for (int i = 0; i < 8 / MW; ++i) {                 // B: 128 rows
                int r = row + i * (MW * 16);
                uint32_t doff = (uint32_t)(r * ROWB + ch * 16);
                cp16(sb + O_BH + doff, Bh + (size_t)(n0 + r) * ldb + k0 + ch * 8);
            }
            cp_commit();
        };

        float acc[4][8][4] = {};

        #pragma unroll
        for (int s = 0; s < STAGES - 1; ++s)
            if (s < nIter) issue(s);

        for (int it = 0; it < nIter; ++it) {
            // Tail-aware wait: group `it` must be complete. Issued so far =
            // min(it+STAGES-1, nIter); allowable pending = issued-(it+1)
            // = min(STAGES-2, nIter-1-it).
            {
                int rem = nIter - 1 - it;
                if (rem >= STAGES - 2) cp_wait<STAGES - 2>();
                else if (rem == 1)     cp_wait<1>();
                else                   cp_wait<0>();
            }
            __syncthreads();

            const uint32_t sb = sbase + (it % STAGES) * STAGEB;
            #pragma unroll
            for (int kk = 0; kk < 32; kk += 16) {
                uint32_t Ahf[4][4], Alf[4][4], Bhf[8][2];

                const uint32_t abase =
                    (uint32_t)(((wm + (lane & 15)) * LDSP + kk + ((lane >> 4) << 3)) * 2);
                #pragma unroll
                for (int mi = 0; mi < 4; ++mi) {
                    ldsm_x4(Ahf[mi][0], Ahf[mi][1], Ahf[mi][2], Ahf[mi][3],
                            sb + O_AH + abase + (uint32_t)(mi * 16 * ROWB));
                    if (NPASS == 2)
                        ldsm_x4(Alf[mi][0], Alf[mi][1], Alf[mi][2], Alf[mi][3],
                                sb + O_AL + abase + (uint32_t)(mi * 16 * ROWB));
                }
                const uint32_t bbase =
                    (uint32_t)(((wn + ((lane >> 4) << 3) + (lane & 7)) * LDSP +
                                kk + (((lane >> 3) & 1) << 3)) * 2);
                #pragma unroll
                for (int nt = 0; nt < 4; ++nt) {
                    ldsm_x4(Bhf[2 * nt][0], Bhf[2 * nt][1],
                            Bhf[2 * nt + 1][0], Bhf[2 * nt + 1][1],
                            sb + O_BH + bbase + (uint32_t)(nt * 16 * ROWB));
                }

                #pragma unroll
                for (int mi = 0; mi < 4; ++mi)
                    #pragma unroll
                    for (int ni = 0; ni < 8; ++ni)
                        mma_f16(acc[mi][ni][0], acc[mi][ni][1], acc[mi][ni][2], acc[mi][ni][3],
                                Ahf[mi][0], Ahf[mi][1], Ahf[mi][2], Ahf[mi][3],
                                Bhf[ni][0], Bhf[ni][1]);
                if (NPASS == 2) {
                    #pragma unroll
                    for (int mi = 0; mi < 4; ++mi)
                        #pragma unroll
                        for (int ni = 0; ni < 8; ++ni)
                            mma_f16(acc[mi][ni][0], acc[mi][ni][1], acc[mi][ni][2], acc[mi][ni][3],
                                    Alf[mi][0], Alf[mi][1], Alf[mi][2], Alf[mi][3],
                                    Bhf[ni][0], Bhf[ni][1]);
                }
            }
            if (it + STAGES - 1 < nIter) issue(it + STAGES - 1);
        }

        // ---- epilogue ----
        if (OMODE == 0) {
            float* C = (float*)Cp0 + (long long)blockIdx.z * sC;
            #pragma unroll
            for (int mi = 0; mi < 4; ++mi) {
                #pragma unroll
                for (int ni = 0; ni < 8; ++ni) {
                    int r = m0 + wm + mi * 16 + (lane >> 2);
                    int c = n0 + wn + ni * 8 + (lane & 3) * 2;
                    *(float2*)&C[(size_t)r * ldc + c] =
                        make_float2(acc[mi][ni][0], acc[mi][ni][1]);
                    *(float2*)&C[(size_t)(r + 8) * ldc + c] =
                        make_float2(acc[mi][ni][2], acc[mi][ni][3]);
                }
            }
        } else {
            f16* Ch = (f16*)Cp0 + (long long)blockIdx.z * sC;
            f16* Cl = (OMODE == 1) ? (f16*)Cp1 + (long long)blockIdx.z * sC : nullptr;
            #pragma unroll
            for (int mi = 0; mi < 4; ++mi) {
                #pragma unroll
                for (int ni = 0; ni < 8; ++ni) {
                    int r = m0 + wm + mi * 16 + (lane >> 2);
                    int c = n0 + wn + ni * 8 + (lane & 3) * 2;
                    #pragma unroll
                    for (int half = 0; half < 2; ++half) {
                        float a0 = acc[mi][ni][2 * half], a1 = acc[mi][ni][2 * half + 1];
                        f16 h0 = __float2half(a0), h1 = __float2half(a1);
                        size_t off = (size_t)(r + half * 8) * ldc + c;
                        *(f162*)&Ch[off] = __halves2half2(h0, h1);
                        if (OMODE == 1)
                            *(f162*)&Cl[off] = __halves2half2(
                                __float2half(a0 - __half2float(h0)),
                                __float2half(a1 - __half2float(h1)));
                    }
                }
            }
        }
    }
}

// ---------------- masked softmax (reads hi/lo logits, writes hi probs) -----
// Zero-fills probs out to a 256-aligned bound so 256-granule K-caps in the
// attn*V GEMM never see raw logits.
__global__ __launch_bounds__(256)
void softmax2(f16* __restrict__ Sh, f16* __restrict__ Sl)
{
    const int t = blockIdx.x;
    const int h = blockIdx.y;
    f162* rowh = (f162*)(Sh + ((size_t)h * TT + t) * TT);
    f162* rowl = (f162*)(Sl + ((size_t)h * TT + t) * TT);

    const float inv = 0.044194173824159216f; // 1/sqrt(512)
    const int tid = threadIdx.x;
    const int boundp = (((t >> 8) + 1) << 8) >> 1;  // 256-aligned, in pairs

    __shared__ float red[256];

    float vals[8];
    float lmax = -INFINITY;
    #pragma unroll
    for (int i = 0; i < 4; ++i) {
        int sp = tid + i * 256;
        if (sp >= boundp) break;
        int s = sp * 2;
        float v0 = -INFINITY, v1 = -INFINITY;
        if (s <= t) {
            float2 vh = __half22float2(rowh[sp]);
            float2 vl = __half22float2(rowl[sp]);
            v0 = (vh.x + vl.x) * inv;
            if (t - s < RA_WIN) v0 *= 1.5f;
            lmax = fmaxf(lmax, v0);
            if (s + 1 <= t) {
                v1 = (vh.y + vl.y) * inv;
                if (t - (s + 1) < RA_WIN) v1 *= 1.5f;
                lmax = fmaxf(lmax, v1);
            }
        }
        vals[2 * i] = v0;
        vals[2 * i + 1] = v1;
    }
    red[tid] = lmax;
    __syncthreads();
    #pragma unroll
    for (int o = 128; o > 0; o >>= 1) {
        if (tid < o) red[tid] = fmaxf(red[tid], red[tid + o]);
        __syncthreads();
    }
    const float m = red[0];
    __syncthreads();

    float lsum = 0.f;
    #pragma unroll
    for (int i = 0; i < 4; ++i) {
        int sp = tid + i * 256;
        if (sp >= boundp) break;
        int s = sp * 2;
        float e0 = 0.f, e1 = 0.f;
        if (s <= t)     { e0 = __expf(vals[2 * i] - m);     lsum += e0; }
        if (s + 1 <= t) { e1 = __expf(vals[2 * i + 1] - m); lsum += e1; }
        vals[2 * i] = e0;
        vals[2 * i + 1] = e1;
    }
    red[tid] = lsum;
    __syncthreads();
    #pragma unroll
    for (int o = 128; o > 0; o >>= 1) {
        if (tid < o) red[tid] += red[tid + o];
        __syncthreads();
    }
    const float inv_sum = 1.0f / red[0];

    #pragma unroll
    for (int i = 0; i < 4; ++i) {
        int sp = tid + i * 256;
        if (sp >= boundp) break;
        rowh[sp] = __halves2half2(
            __float2half(vals[2 * i] * inv_sum),
            __float2half(vals[2 * i + 1] * inv_sum));
    }
}

// ---------------- launch ----------------
extern "C" void kernel_launch(void* const* d_in, const int* in_sizes, int n_in,
                              void* d_out, int out_size)
{
    const float* hidden = (const float*)d_in[0]; // [T, E]
    const float* w_q    = (const float*)d_in[1]; // [E, E]
    const float* w_kd   = (const float*)d_in[2]; // [L, E]
    const float* w_vd   = (const float*)d_in[3]; // [L, E]
    const float* q2l    = (const float*)d_in[4]; // [H, D, L]
    const float* v_up   = (const float*)d_in[5]; // [H, L, D]
    const float* w_out  = (const float*)d_in[6]; // [E, E]
    float* out = (float*)d_out;                  // [T, E]

    f16 *hidh, *hidl, *wqh, *wkdh, *wvdh, *wouth, *q2lTh, *vupTh;
    f16 *Qh, *Ql, *latkh, *latkl, *latvh, *latvl, *qlath, *qlatl;
    f16 *Vh, *VTh, *Sh, *Sl, *ctxh;
    cudaGetSymbolAddress((void**)&hidh, g_hidh);   cudaGetSymbolAddress((void**)&hidl, g_hidl);
    cudaGetSymbolAddress((void**)&wqh, g_wqh);
    cudaGetSymbolAddress((void**)&wkdh, g_wkdh);
    cudaGetSymbolAddress((void**)&wvdh, g_wvdh);
    cudaGetSymbolAddress((void**)&wouth, g_wouth);
    cudaGetSymbolAddress((void**)&q2lTh, g_q2lTh);
    cudaGetSymbolAddress((void**)&vupTh, g_vupTh);
    cudaGetSymbolAddress((void**)&Qh, g_Qh);       cudaGetSymbolAddress((void**)&Ql, g_Ql);
    cudaGetSymbolAddress((void**)&latkh, g_latkh); cudaGetSymbolAddress((void**)&latkl, g_latkl);
    cudaGetSymbolAddress((void**)&latvh, g_latvh); cudaGetSymbolAddress((void**)&latvl, g_latvl);
    cudaGetSymbolAddress((void**)&qlath, g_qlath); cudaGetSymbolAddress((void**)&qlatl, g_qlatl);
    cudaGetSymbolAddress((void**)&Vh, g_Vh);
    cudaGetSymbolAddress((void**)&VTh, g_VTh);
    cudaGetSymbolAddress((void**)&Sh, g_Sh);       cudaGetSymbolAddress((void**)&Sl, g_Sl);
    cudaGetSymbolAddress((void**)&ctxh, g_ctxh);

    // smem sizes
    const int SM_2_2 = 3 * (2 * 128 * ROWB + BTILEB);   // 92160
    const int SM_2_4 = 3 * (2 * 256 * ROWB + BTILEB);   // 153600
    const int SM_1_2 = 4 * (1 * 128 * ROWB + BTILEB);   // 81920 (4-stage)
    const int SM_1_4 = 4 * (1 * 256 * ROWB + BTILEB);   // 122880 (4-stage)
    cudaFuncSetAttribute(gemm2<1, 2, 2>, cudaFuncAttributeMaxDynamicSharedMemorySize, SM_2_2);
    cudaFuncSetAttribute(gemm2<2, 2, 2>, cudaFuncAttributeMaxDynamicSharedMemorySize, SM_2_2);
    cudaFuncSetAttribute(gemm2<1, 2, 4>, cudaFuncAttributeMaxDynamicSharedMemorySize, SM_2_4);
    cudaFuncSetAttribute(gemm2<2, 1, 2>, cudaFuncAttributeMaxDynamicSharedMemorySize, SM_1_2);
    cudaFuncSetAttribute(gemm2<0, 1, 4>, cudaFuncAttributeMaxDynamicSharedMemorySize, SM_1_4);

    // ---- conversions ----
    split_k<<<(TT * EE / 4 + 255) / 256, 256>>>(hidden, hidh, hidl, TT * EE / 4);
    split_k1<<<(EE * EE / 4 + 255) / 256, 256>>>(w_q, wqh, EE * EE / 4);
    split_k1<<<(LL * EE / 4 + 255) / 256, 256>>>(w_kd, wkdh, LL * EE / 4);
    split_k1<<<(LL * EE / 4 + 255) / 256, 256>>>(w_vd, wvdh, LL * EE / 4);
    split_k1<<<(EE * EE / 4 + 255) / 256, 256>>>(w_out, wouth, EE * EE / 4);
    transposeH<<<dim3(LL / 32, DD / 32, HH), dim3(32, 8)>>>(q2l, q2lTh, DD, LL);
    transposeH<<<dim3(DD / 32, LL / 32, HH), dim3(32, 8)>>>(v_up, vupTh, LL, DD);

    // 1) Q = hidden @ w_q^T  [2048,2048,2048]  (2-pass, hi/lo out, 256-tile)
    gemm2<1, 2, 4><<<dim3(EE / 128, TT / 256, 1), dim3(256), SM_2_4>>>(
        hidh, hidl, EE, 0, wqh, EE, 0, Qh, Ql, EE, 0, EE, 0,
        nullptr, nullptr, nullptr);

    // 2+3) latent_k / latent_v fused (z=0 -> latk, z=1 -> latv), 2-pass hi/lo
    gemm2<1, 2, 2><<<dim3(LL / 128, TT / 128, 2), dim3(128), SM_2_2>>>(
        hidh, hidl, EE, 0, wkdh, EE, 0, latkh, latkl, LL, 0, EE, 0,
        wvdh, latvh, latvl);

    // 4) q_latent[h] = Q[:,hD:] @ q2lT[h]^T  [2048,512,128]  (2-pass, hi/lo)
    gemm2<1, 2, 2><<<dim3(LL / 128, TT / 128, HH), dim3(128), SM_2_2>>>(
        Qh, Ql, EE, DD, q2lTh, DD, (long long)LL * DD,
        qlath, qlatl, LL, (long long)TT * LL, DD, 0,
        nullptr, nullptr, nullptr);

    // 5) V[:,h] = latent_v @ vupT[h]^T  [2048,128,512]  (2-pass, hi-only out)
    gemm2<2, 2, 2><<<dim3(DD / 128, TT / 128, HH), dim3(128), SM_2_2>>>(
        latvh, latvl, LL, 0, vupTh, LL, (long long)DD * LL,
        Vh, nullptr, EE, DD, LL, 0,
        nullptr, nullptr, nullptr);

    // 6) S[h] = q_latent[h] @ latent_k^T  [2048,2048,512]
    //    causal tile skip, 2-pass, hi/lo logits out, 256-tile
    gemm2<1, 2, 4><<<dim3(TT / 128, TT / 256, HH), dim3(256), SM_2_4>>>(
        qlath, qlatl, LL, (long long)TT * LL, latkh, LL, 0,
        Sh, Sl, TT, (long long)TT * TT, LL, 1,
        nullptr, nullptr, nullptr);

    // 7) V^T: [T][E] -> [E][T]  (hi only)
    transpose1<<<dim3(EE / 32, TT / 32), dim3(32, 8)>>>(Vh, VTh, TT, EE);

    // 8) masked softmax: read hi/lo logits, write hi probs, 256-aligned bound
    softmax2<<<dim3(TT, HH), dim3(256)>>>(Sh, Sl);

    // 9) ctx[:,h] = attn[h] @ VT[h]^T  [2048,128,2048]
    //    PAIR-BALANCED K-cap (mode 3): grid y=8, each CTA does tiles y & 15-y
    //    1-pass, hi-only ctx out, 128-tile, 4-stage pipeline
    gemm2<2, 1, 2><<<dim3(DD / 128, TT / 256, HH), dim3(128), SM_1_2>>>(
        Sh, nullptr, TT, (long long)TT * TT, VTh, TT, (long long)DD * TT,
        ctxh, nullptr, EE, DD, TT, 3,
        nullptr, nullptr, nullptr);

    // 10) out = ctx @ w_out^T  [2048,2048,2048]  (1-pass, fp32 out, 256-tile)
    gemm2<0, 1, 4><<<dim3(EE / 128, TT / 256, 1), dim3(256), SM_1_4>>>(
        ctxh, nullptr, EE, 0, wouth, EE, 0, out, nullptr, EE, 0, EE, 0,
        nullptr, nullptr, nullptr);
}

// round 16
// speedup vs baseline: 1.0533x; 1.0160x over previous
#include <cuda_runtime.h>
#include <cuda_fp16.h>
#include <math.h>
#include <stdint.h>

// Problem dims (fixed by the reference)
#define TT 2048   // tokens
#define EE 2048   // embed
#define HH 16     // heads
#define LL 512    // latent
#define DD 128    // head dim
#define RA_WIN 64

typedef __half f16;
typedef __half2 f162;

// ---------------- scratch (allocation-free: device globals) ----------------
__device__ f16 g_hidh[TT * EE],  g_hidl[TT * EE];
__device__ f16 g_wqh[EE * EE];
__device__ f16 g_wkdh[LL * EE];
__device__ f16 g_wvdh[LL * EE];
__device__ f16 g_wouth[EE * EE];
__device__ f16 g_q2lTh[HH * LL * DD];                    // [H][L][D]
__device__ f16 g_vupTh[HH * DD * LL], g_vupTl[HH * DD * LL]; // [H][D][L] hi/lo
__device__ f16 g_Qh[TT * EE],   g_Ql[TT * EE];
__device__ f16 g_latkh[TT * LL];
__device__ f16 g_latvh[TT * LL];
__device__ f16 g_qlath[(size_t)HH * TT * LL], g_qlatl[(size_t)HH * TT * LL];
__device__ f16 g_VTh[EE * TT];                 // [H*D][T] (written directly)
__device__ f16 g_Sh[(size_t)HH * TT * TT], g_Sl[(size_t)HH * TT * TT];
__device__ f16 g_ctxh[TT * EE];

// ---------------- helpers ----------------
__device__ __forceinline__ uint32_t smem_u32(const void* p) {
    uint32_t a;
    asm("{ .reg .u64 t; cvta.to.shared.u64 t, %1; cvt.u32.u64 %0, t; }"
        : "=r"(a) : "l"(p));
    return a;
}

__device__ __forceinline__ void cp16(uint32_t dst, const void* src) {
    asm volatile("cp.async.cg.shared.global [%0], [%1], 16;" :: "r"(dst), "l"(src));
}
__device__ __forceinline__ void cp_commit() {
    asm volatile("cp.async.commit_group;" ::: "memory");
}
template <int N>
__device__ __forceinline__ void cp_wait() {
    asm volatile("cp.async.wait_group %0;" :: "n"(N) : "memory");
}

__device__ __forceinline__ void ldsm_x4(uint32_t& r0, uint32_t& r1,
                                        uint32_t& r2, uint32_t& r3,
                                        uint32_t addr) {
    asm volatile("ldmatrix.sync.aligned.m8n8.x4.shared.b16 {%0,%1,%2,%3}, [%4];\n"
                 : "=r"(r0), "=r"(r1), "=r"(r2), "=r"(r3)
                 : "r"(addr));
}

__device__ __forceinline__ void mma_f16(float& c0, float& c1, float& c2, float& c3,
                                        uint32_t a0, uint32_t a1, uint32_t a2, uint32_t a3,
                                        uint32_t b0, uint32_t b1) {
    asm volatile("mma.sync.aligned.m16n8k16.row.col.f32.f16.f16.f32 "
                 "{%0,%1,%2,%3}, {%4,%5,%6,%7}, {%8,%9}, {%0,%1,%2,%3};\n"
                 : "+f"(c0), "+f"(c1), "+f"(c2), "+f"(c3)
                 : "r"(a0), "r"(a1), "r"(a2), "r"(a3), "r"(b0), "r"(b1));
}

// ---------------- conversion kernels ----------------
__global__ __launch_bounds__(256)
void split_k(const float* __restrict__ in, f16* __restrict__ h,
             f16* __restrict__ l, int n4)
{
    int i = blockIdx.x * blockDim.x + threadIdx.x;
    if (i >= n4) return;
    float4 v = ((const float4*)in)[i];
    f16 hx = __float2half(v.x), hy = __float2half(v.y);
    f16 hz = __float2half(v.z), hw = __float2half(v.w);
    ((f162*)h)[2 * i]     = __halves2half2(hx, hy);
    ((f162*)h)[2 * i + 1] = __halves2half2(hz, hw);
    ((f162*)l)[2 * i] = __halves2half2(
        __float2half(v.x - __half2float(hx)),
        __float2half(v.y - __half2float(hy)));
    ((f162*)l)[2 * i + 1] = __halves2half2(
        __float2half(v.z - __half2float(hz)),
        __float2half(v.w - __half2float(hw)));
}

__global__ __launch_bounds__(256)
void split_k1(const float* __restrict__ in, f16* __restrict__ h, int n4)
{
    int i = blockIdx.x * blockDim.x + threadIdx.x;
    if (i >= n4) return;
    float4 v = ((const float4*)in)[i];
    ((f162*)h)[2 * i]     = __halves2half2(__float2half(v.x), __float2half(v.y));
    ((f162*)h)[2 * i + 1] = __halves2half2(__float2half(v.z), __float2half(v.w));
}

// in [z][R][C] fp32 -> out [z][C][R] hi/lo f16 (tiled transpose)
__global__ __launch_bounds__(256)
void transposeSplit(const float* __restrict__ in, f16* __restrict__ outh,
                    f16* __restrict__ outl, int R, int C)
{
    __shared__ float t[32][33];
    const size_t zoff = (size_t)blockIdx.z * R * C;
    in += zoff; outh += zoff; outl += zoff;
    const int c0 = blockIdx.x * 32, r0 = blockIdx.y * 32;
    const int tx = threadIdx.x;
    for (int i = threadIdx.y; i < 32; i += 8)
        t[i][tx] = in[(size_t)(r0 + i) * C + c0 + tx];
    __syncthreads();
    for (int i = threadIdx.y; i < 32; i += 8) {
        float v = t[tx][i];
        f16 hh = __float2half(v);
        outh[(size_t)(c0 + i) * R + r0 + tx] = hh;
        outl[(size_t)(c0 + i) * R + r0 + tx] =
            __float2half(v - __half2float(hh));
    }
}

// in [z][R][C] fp32 -> out [z][C][R] f16 hi only
__global__ __launch_bounds__(256)
void transposeH(const float* __restrict__ in, f16* __restrict__ outh,
                int R, int C)
{
    __shared__ float t[32][33];
    const size_t zoff = (size_t)blockIdx.z * R * C;
    in += zoff; outh += zoff;
    const int c0 = blockIdx.x * 32, r0 = blockIdx.y * 32;
    const int tx = threadIdx.x;
    for (int i = threadIdx.y; i < 32; i += 8)
        t[i][tx] = in[(size_t)(r0 + i) * C + c0 + tx];
    __syncthreads();
    for (int i = threadIdx.y; i < 32; i += 8)
        outh[(size_t)(c0 + i) * R + r0 + tx] = __float2half(t[tx][i]);
}

// ---------------- split-fp16 NT GEMM (cp.async pipelined) ----------------
// C[M,N] = A @ B^T, fp32 acc, cp.async pipeline, CTA (MW*64)x128, BK=32.
// MW: 2 -> 128x128 CTA (4 warps, 2 CTAs/SM); 4 -> 256x128 (8 warps, 1 CTA/SM).
// NPASS=2: A=(Ah+Al), B=Bh, 2 passes, 3 stages. NPASS=1: single pass, 4 stages.
// OMODE: 0 = fp32 C, 1 = hi/lo f16 C, 2 = hi-only f16 C.
// mode: 0 plain; 1 causal tile skip; 2 K-cap at (y+1)*MROWS;
//       3 PAIR-BALANCED K-cap: CTA does m-tiles y and (2*gridDim.y-1-y).
// Tail wait is remaining-groups aware.
// BhAlt/CAlt: when non-null and blockIdx.z==1, swap B/C pointers (fused dual GEMM).
#define LDSP 40                    // padded row in f16 elems (80B)
#define ROWB (LDSP * 2)            // 80
#define BTILEB (128 * ROWB)        // 10240

template <int OMODE, int NPASS, int MW>
__global__ __launch_bounds__(MW * 64, 4 / MW)
void gemm2(const f16* __restrict__ Ah, const f16* __restrict__ Al,
           int lda, long long sA,
           const f16* __restrict__ Bh,
           int ldb, long long sB,
           void* __restrict__ Cp0, void* __restrict__ Cp1,
           int ldc, long long sC, int K, int mode,
           const f16* __restrict__ BhAlt,
           void* __restrict__ CAlt0, void* __restrict__ CAlt1)
{
    constexpr int MROWS = MW * 64;
    if (mode == 1 && (int)(blockIdx.x * 128) >= (int)((blockIdx.y + 1) * MROWS)) return;

    constexpr int ATILEB = MROWS * ROWB;
    constexpr int STAGES = (NPASS == 1) ? 4 : 3;
    constexpr int STAGEB = ((NPASS == 2) ? 2 : 1) * ATILEB + BTILEB;
    constexpr uint32_t O_AH = 0;
    constexpr uint32_t O_AL = ATILEB;                      // only if NPASS==2
    constexpr uint32_t O_BH = ((NPASS == 2) ? 2 : 1) * ATILEB;

    extern __shared__ char smem[];
    const uint32_t sbase = smem_u32(smem);
    const int tid = threadIdx.x;
    const int lane = tid & 31;
    const int wid = tid >> 5;
    const int wm = (wid >> 1) * 64;
    const int wn = (wid & 1) * 64;

    if (BhAlt && blockIdx.z) {
        Bh = BhAlt; Cp0 = CAlt0; Cp1 = CAlt1;
    }
    Ah += (long long)blockIdx.z * sA;
    if (NPASS == 2) Al += (long long)blockIdx.z * sA;
    Bh += (long long)blockIdx.z * sB;
    const int n0 = blockIdx.x * 128;

    const int row = tid >> 2;      // 0 .. MW*16-1
    const int ch = tid & 3;

    const int ntile = (mode == 3) ? 2 : 1;

    for (int ti = 0; ti < ntile; ++ti) {
        const int yb = (ti == 0) ? (int)blockIdx.y
                                 : (int)(2 * gridDim.y - 1 - blockIdx.y);
        const int m0 = yb * MROWS;

        int nIter = K >> 5;
        if (mode == 2 || mode == 3) {
            int kc = (yb + 1) * MROWS;
            if (kc < K) nIter = kc >> 5;
        }

        if (ti) __syncthreads();   // protect smem stages between tiles

        auto issue = [&](int g) {
            const int k0 = g << 5;
            const uint32_t sb = sbase + (g % STAGES) * STAGEB;
            #pragma unroll
            for (int i = 0; i < 4; ++i) {                      // A: MROWS rows
                int r = row + i * (MW * 16);
                uint32_t doff = (uint32_t)(r * ROWB + ch * 16);
                cp16(sb + O_AH + doff, Ah + (size_t)(m0 + r) * lda + k0 + ch * 8);
                if (NPASS == 2)
                    cp16(sb + O_AL + doff, Al + (size_t)(m0 + r) * lda + k0 + ch * 8);
            }
            #pragma unroll
            for (int i = 0; i < 8 / MW; ++i) {                 // B: 128 rows
                int r = row + i * (MW * 16);
                uint32_t doff = (uint32_t)(r * ROWB + ch * 16);
                cp16(sb + O_BH + doff, Bh + (size_t)(n0 + r) * ldb + k0 + ch * 8);
            }
            cp_commit();
        };

        float acc[4][8][4] = {};

        #pragma unroll
        for (int s = 0; s < STAGES - 1; ++s)
            if (s < nIter) issue(s);

        for (int it = 0; it < nIter; ++it) {
            // Tail-aware wait: allowable pending = min(STAGES-2, nIter-1-it).
            {
                int rem = nIter - 1 - it;
                if (rem >= STAGES - 2) cp_wait<STAGES - 2>();
                else if (rem == 1)     cp_wait<1>();
                else                   cp_wait<0>();
            }
            __syncthreads();

            const uint32_t sb = sbase + (it % STAGES) * STAGEB;
            #pragma unroll
            for (int kk = 0; kk < 32; kk += 16) {
                uint32_t Ahf[4][4], Alf[4][4], Bhf[8][2];

                const uint32_t abase =
                    (uint32_t)(((wm + (lane & 15)) * LDSP + kk + ((lane >> 4) << 3)) * 2);
                #pragma unroll
                for (int mi = 0; mi < 4; ++mi) {
                    ldsm_x4(Ahf[mi][0], Ahf[mi][1], Ahf[mi][2], Ahf[mi][3],
                            sb + O_AH + abase + (uint32_t)(mi * 16 * ROWB));
                    if (NPASS == 2)
                        ldsm_x4(Alf[mi][0], Alf[mi][1], Alf[mi][2], Alf[mi][3],
                                sb + O_AL + abase + (uint32_t)(mi * 16 * ROWB));
                }
                const uint32_t bbase =
                    (uint32_t)(((wn + ((lane >> 4) << 3) + (lane & 7)) * LDSP +
                                kk + (((lane >> 3) & 1) << 3)) * 2);
                #pragma unroll
                for (int nt = 0; nt < 4; ++nt) {
                    ldsm_x4(Bhf[2 * nt][0], Bhf[2 * nt][1],
                            Bhf[2 * nt + 1][0], Bhf[2 * nt + 1][1],
                            sb + O_BH + bbase + (uint32_t)(nt * 16 * ROWB));
                }

                #pragma unroll
                for (int mi = 0; mi < 4; ++mi)
                    #pragma unroll
                    for (int ni = 0; ni < 8; ++ni)
                        mma_f16(acc[mi][ni][0], acc[mi][ni][1], acc[mi][ni][2], acc[mi][ni][3],
                                Ahf[mi][0], Ahf[mi][1], Ahf[mi][2], Ahf[mi][3],
                                Bhf[ni][0], Bhf[ni][1]);
                if (NPASS == 2) {
                    #pragma unroll
                    for (int mi = 0; mi < 4; ++mi)
                        #pragma unroll
                        for (int ni = 0; ni < 8; ++ni)
                            mma_f16(acc[mi][ni][0], acc[mi][ni][1], acc[mi][ni][2], acc[mi][ni][3],
                                    Alf[mi][0], Alf[mi][1], Alf[mi][2], Alf[mi][3],
                                    Bhf[ni][0], Bhf[ni][1]);
                }
            }
            if (it + STAGES - 1 < nIter) issue(it + STAGES - 1);
        }

        // ---- epilogue ----
        if (OMODE == 0) {
            float* C = (float*)Cp0 + (long long)blockIdx.z * sC;
            #pragma unroll
            for (int mi = 0; mi < 4; ++mi) {
                #pragma unroll
                for (int ni = 0; ni < 8; ++ni) {
                    int r = m0 + wm + mi * 16 + (lane >> 2);
                    int c = n0 + wn + ni * 8 + (lane & 3) * 2;
                    *(float2*)&C[(size_t)r * ldc + c] =
                        make_float2(acc[mi][ni][0], acc[mi][ni][1]);
                    *(float2*)&C[(size_t)(r + 8) * ldc + c] =
                        make_float2(acc[mi][ni][2], acc[mi][ni][3]);
                }
            }
        } else {
            f16* Ch = (f16*)Cp0 + (long long)blockIdx.z * sC;
            f16* Cl = (OMODE == 1) ? (f16*)Cp1 + (long long)blockIdx.z * sC : nullptr;
            #pragma unroll
            for (int mi = 0; mi < 4; ++mi) {
                #pragma unroll
                for (int ni = 0; ni < 8; ++ni) {
                    int r = m0 + wm + mi * 16 + (lane >> 2);
                    int c = n0 + wn + ni * 8 + (lane & 3) * 2;
                    #pragma unroll
                    for (int half = 0; half < 2; ++half) {
                        float a0 = acc[mi][ni][2 * half], a1 = acc[mi][ni][2 * half + 1];
                        f16 h0 = __float2half(a0), h1 = __float2half(a1);
                        size_t off = (size_t)(r + half * 8) * ldc + c;
                        *(f162*)&Ch[off] = __halves2half2(h0, h1);
                        if (OMODE == 1)
                            *(f162*)&Cl[off] = __halves2half2(
                                __float2half(a0 - __half2float(h0)),
                                __float2half(a1 - __half2float(h1)));
                    }
                }
            }
        }
    }
}

// ---------------- masked softmax (reads hi/lo logits, writes hi probs) -----
// Zero-fills probs out to a 256-aligned bound so 256-granule K-caps in the
// attn*V GEMM never see raw logits.
__global__ __launch_bounds__(256)
void softmax2(f16* __restrict__ Sh, f16* __restrict__ Sl)
{
    const int t = blockIdx.x;
    const int h = blockIdx.y;
    f162* rowh = (f162*)(Sh + ((size_t)h * TT + t) * TT);
    f162* rowl = (f162*)(Sl + ((size_t)h * TT + t) * TT);

    const float inv = 0.044194173824159216f; // 1/sqrt(512)
    const int tid = threadIdx.x;
    const int boundp = (((t >> 8) + 1) << 8) >> 1;  // 256-aligned, in pairs

    __shared__ float red[256];

    float vals[8];
    float lmax = -INFINITY;
    #pragma unroll
    for (int i = 0; i < 4; ++i) {
        int sp = tid + i * 256;
        if (sp >= boundp) break;
        int s = sp * 2;
        float v0 = -INFINITY, v1 = -INFINITY;
        if (s <= t) {
            float2 vh = __half22float2(rowh[sp]);
            float2 vl = __half22float2(rowl[sp]);
            v0 = (vh.x + vl.x) * inv;
            if (t - s < RA_WIN) v0 *= 1.5f;
            lmax = fmaxf(lmax, v0);
            if (s + 1 <= t) {
                v1 = (vh.y + vl.y) * inv;
                if (t - (s + 1) < RA_WIN) v1 *= 1.5f;
                lmax = fmaxf(lmax, v1);
            }
        }
        vals[2 * i] = v0;
        vals[2 * i + 1] = v1;
    }
    red[tid] = lmax;
    __syncthreads();
    #pragma unroll
    for (int o = 128; o > 0; o >>= 1) {
        if (tid < o) red[tid] = fmaxf(red[tid], red[tid + o]);
        __syncthreads();
    }
    const float m = red[0];
    __syncthreads();

    float lsum = 0.f;
    #pragma unroll
    for (int i = 0; i < 4; ++i) {
        int sp = tid + i * 256;
        if (sp >= boundp) break;
        int s = sp * 2;
        float e0 = 0.f, e1 = 0.f;
        if (s <= t)     { e0 = __expf(vals[2 * i] - m);     lsum += e0; }
        if (s + 1 <= t) { e1 = __expf(vals[2 * i + 1] - m); lsum += e1; }
        vals[2 * i] = e0;
        vals[2 * i + 1] = e1;
    }
    red[tid] = lsum;
    __syncthreads();
    #pragma unroll
    for (int o = 128; o > 0; o >>= 1) {
        if (tid < o) red[tid] += red[tid + o];
        __syncthreads();
    }
    const float inv_sum = 1.0f / red[0];

    #pragma unroll
    for (int i = 0; i < 4; ++i) {
        int sp = tid + i * 256;
        if (sp >= boundp) break;
        rowh[sp] = __halves2half2(
            __float2half(vals[2 * i] * inv_sum),
            __float2half(vals[2 * i + 1] * inv_sum));
    }
}

// ---------------- launch ----------------
extern "C" void kernel_launch(void* const* d_in, const int* in_sizes, int n_in,
                              void* d_out, int out_size)
{
    const float* hidden = (const float*)d_in[0]; // [T, E]
    const float* w_q    = (const float*)d_in[1]; // [E, E]
    const float* w_kd   = (const float*)d_in[2]; // [L, E]
    const float* w_vd   = (const float*)d_in[3]; // [L, E]
    const float* q2l    = (const float*)d_in[4]; // [H, D, L]
    const float* v_up   = (const float*)d_in[5]; // [H, L, D]
    const float* w_out  = (const float*)d_in[6]; // [E, E]
    float* out = (float*)d_out;                  // [T, E]

    f16 *hidh, *hidl, *wqh, *wkdh, *wvdh, *wouth, *q2lTh, *vupTh, *vupTl;
    f16 *Qh, *Ql, *latkh, *latvh, *qlath, *qlatl;
    f16 *VTh, *Sh, *Sl, *ctxh;
    cudaGetSymbolAddress((void**)&hidh, g_hidh);   cudaGetSymbolAddress((void**)&hidl, g_hidl);
    cudaGetSymbolAddress((void**)&wqh, g_wqh);
    cudaGetSymbolAddress((void**)&wkdh, g_wkdh);
    cudaGetSymbolAddress((void**)&wvdh, g_wvdh);
    cudaGetSymbolAddress((void**)&wouth, g_wouth);
    cudaGetSymbolAddress((void**)&q2lTh, g_q2lTh);
    cudaGetSymbolAddress((void**)&vupTh, g_vupTh); cudaGetSymbolAddress((void**)&vupTl, g_vupTl);
    cudaGetSymbolAddress((void**)&Qh, g_Qh);       cudaGetSymbolAddress((void**)&Ql, g_Ql);
    cudaGetSymbolAddress((void**)&latkh, g_latkh);
    cudaGetSymbolAddress((void**)&latvh, g_latvh);
    cudaGetSymbolAddress((void**)&qlath, g_qlath); cudaGetSymbolAddress((void**)&qlatl, g_qlatl);
    cudaGetSymbolAddress((void**)&VTh, g_VTh);
    cudaGetSymbolAddress((void**)&Sh, g_Sh);       cudaGetSymbolAddress((void**)&Sl, g_Sl);
    cudaGetSymbolAddress((void**)&ctxh, g_ctxh);

    // smem sizes
    const int SM_2_2 = 3 * (2 * 128 * ROWB + BTILEB);   // 92160
    const int SM_2_4 = 3 * (2 * 256 * ROWB + BTILEB);   // 153600
    const int SM_1_2 = 4 * (1 * 128 * ROWB + BTILEB);   // 81920 (4-stage)
    const int SM_1_4 = 4 * (1 * 256 * ROWB + BTILEB);   // 122880 (4-stage)
    cudaFuncSetAttribute(gemm2<1, 2, 2>, cudaFuncAttributeMaxDynamicSharedMemorySize, SM_2_2);
    cudaFuncSetAttribute(gemm2<2, 2, 2>, cudaFuncAttributeMaxDynamicSharedMemorySize, SM_2_2);
    cudaFuncSetAttribute(gemm2<1, 2, 4>, cudaFuncAttributeMaxDynamicSharedMemorySize, SM_2_4);
    cudaFuncSetAttribute(gemm2<2, 1, 2>, cudaFuncAttributeMaxDynamicSharedMemorySize, SM_1_2);
    cudaFuncSetAttribute(gemm2<0, 1, 4>, cudaFuncAttributeMaxDynamicSharedMemorySize, SM_1_4);

    // ---- conversions ----
    split_k<<<(TT * EE / 4 + 255) / 256, 256>>>(hidden, hidh, hidl, TT * EE / 4);
    split_k1<<<(EE * EE / 4 + 255) / 256, 256>>>(w_q, wqh, EE * EE / 4);
    split_k1<<<(LL * EE / 4 + 255) / 256, 256>>>(w_kd, wkdh, LL * EE / 4);
    split_k1<<<(LL * EE / 4 + 255) / 256, 256>>>(w_vd, wvdh, LL * EE / 4);
    split_k1<<<(EE * EE / 4 + 255) / 256, 256>>>(w_out, wouth, EE * EE / 4);
    transposeH<<<dim3(LL / 32, DD / 32, HH), dim3(32, 8)>>>(q2l, q2lTh, DD, LL);
    // vup transposed with hi/lo (A operand of the VT GEMM; recovered in 2-pass)
    transposeSplit<<<dim3(DD / 32, LL / 32, HH), dim3(32, 8)>>>(v_up, vupTh, vupTl, LL, DD);

    // 1) Q = hidden @ w_q^T  [2048,2048,2048]  (2-pass, hi/lo out, 256-tile)
    gemm2<1, 2, 4><<<dim3(EE / 128, TT / 256, 1), dim3(256), SM_2_4>>>(
        hidh, hidl, EE, 0, wqh, EE, 0, Qh, Ql, EE, 0, EE, 0,
        nullptr, nullptr, nullptr);

    // 2+3) latent_k / latent_v fused (z=0 -> latk, z=1 -> latv), 2-pass
    //      hi-only outputs (latv lo no longer consumed anywhere)
    gemm2<2, 2, 2><<<dim3(LL / 128, TT / 128, 2), dim3(128), SM_2_2>>>(
        hidh, hidl, EE, 0, wkdh, EE, 0, latkh, nullptr, LL, 0, EE, 0,
        wvdh, latvh, nullptr);

    // 4) q_latent[h] = Q[:,hD:] @ q2lT[h]^T  [2048,512,128]  (2-pass, hi/lo)
    gemm2<1, 2, 2><<<dim3(LL / 128, TT / 128, HH), dim3(128), SM_2_2>>>(
        Qh, Ql, EE, DD, q2lTh, DD, (long long)LL * DD,
        qlath, qlatl, LL, (long long)TT * LL, DD, 0,
        nullptr, nullptr, nullptr);

    // 5) VT[h] = vupT[h] @ latv^T  [128,2048,512]  (2-pass: vup recovered,
    //    latv rounded; writes V TRANSPOSED directly -> no transpose kernel)
    gemm2<2, 2, 2><<<dim3(TT / 128, 1, HH), dim3(128), SM_2_2>>>(
        vupTh, vupTl, LL, (long long)DD * LL, latvh, LL, 0,
        VTh, nullptr, TT, (long long)DD * TT, LL, 0,
        nullptr, nullptr, nullptr);

    // 6) S[h] = q_latent[h] @ latent_k^T  [2048,2048,512]
    //    causal tile skip, 2-pass, hi/lo logits out, 256-tile
    gemm2<1, 2, 4><<<dim3(TT / 128, TT / 256, HH), dim3(256), SM_2_4>>>(
        qlath, qlatl, LL, (long long)TT * LL, latkh, LL, 0,
        Sh, Sl, TT, (long long)TT * TT, LL, 1,
        nullptr, nullptr, nullptr);

    // 7) masked softmax: read hi/lo logits, write hi probs, 256-aligned bound
    softmax2<<<dim3(TT, HH), dim3(256)>>>(Sh, Sl);

    // 8) ctx[:,h] = attn[h] @ VT[h]^T  [2048,128,2048]
    //    PAIR-BALANCED K-cap (mode 3), 1-pass, hi-only ctx out, 4-stage
    gemm2<2, 1, 2><<<dim3(DD / 128, TT / 256, HH), dim3(128), SM_1_2>>>(
        Sh, nullptr, TT, (long long)TT * TT, VTh, TT, (long long)DD * TT,
        ctxh, nullptr, EE, DD, TT, 3,
        nullptr, nullptr, nullptr);

    // 9) out = ctx @ w_out^T  [2048,2048,2048]  (1-pass, fp32 out, 256-tile)
    gemm2<0, 1, 4><<<dim3(EE / 128, TT / 256, 1), dim3(256), SM_1_4>>>(
        ctxh, nullptr, EE, 0, wouth, EE, 0, out, nullptr, EE, 0, EE, 0,
        nullptr, nullptr, nullptr);
}

// round 17
// speedup vs baseline: 1.1154x; 1.0590x over previous
#include <cuda_runtime.h>
#include <cuda_fp16.h>
#include <math.h>
#include <stdint.h>

// Problem dims (fixed by the reference)
#define TT 2048   // tokens
#define EE 2048   // embed
#define HH 16     // heads
#define LL 512    // latent
#define DD 128    // head dim
#define RA_WIN 64

typedef __half f16;
typedef __half2 f162;

// ---------------- scratch (allocation-free: device globals) ----------------
__device__ f16 g_hidh[TT * EE],  g_hidl[TT * EE];
__device__ f16 g_wqh[EE * EE];
__device__ f16 g_wkdh[LL * EE];
__device__ f16 g_wvdh[LL * EE];
__device__ f16 g_wouth[EE * EE];
__device__ f16 g_q2lTh[HH * LL * DD];                    // [H][L][D]
__device__ f16 g_vupTh[HH * DD * LL], g_vupTl[HH * DD * LL]; // [H][D][L] hi/lo
__device__ f16 g_Qh[TT * EE],   g_Ql[TT * EE];
__device__ f16 g_latkh[TT * LL];
__device__ f16 g_latvh[TT * LL];
__device__ f16 g_qlath[(size_t)HH * TT * LL], g_qlatl[(size_t)HH * TT * LL];
__device__ f16 g_VTh[EE * TT];                 // [H*D][T] (written directly)
__device__ f16 g_Sh[(size_t)HH * TT * TT], g_Sl[(size_t)HH * TT * TT];
__device__ f16 g_ctxh[TT * EE];

// ---------------- helpers ----------------
__device__ __forceinline__ uint32_t smem_u32(const void* p) {
    uint32_t a;
    asm("{ .reg .u64 t; cvta.to.shared.u64 t, %1; cvt.u32.u64 %0, t; }"
        : "=r"(a) : "l"(p));
    return a;
}

__device__ __forceinline__ void cp16(uint32_t dst, const void* src) {
    asm volatile("cp.async.cg.shared.global [%0], [%1], 16;" :: "r"(dst), "l"(src));
}
__device__ __forceinline__ void cp_commit() {
    asm volatile("cp.async.commit_group;" ::: "memory");
}
template <int N>
__device__ __forceinline__ void cp_wait() {
    asm volatile("cp.async.wait_group %0;" :: "n"(N) : "memory");
}

__device__ __forceinline__ void ldsm_x4(uint32_t& r0, uint32_t& r1,
                                        uint32_t& r2, uint32_t& r3,
                                        uint32_t addr) {
    asm volatile("ldmatrix.sync.aligned.m8n8.x4.shared.b16 {%0,%1,%2,%3}, [%4];\n"
                 : "=r"(r0), "=r"(r1), "=r"(r2), "=r"(r3)
                 : "r"(addr));
}

__device__ __forceinline__ void mma_f16(float& c0, float& c1, float& c2, float& c3,
                                        uint32_t a0, uint32_t a1, uint32_t a2, uint32_t a3,
                                        uint32_t b0, uint32_t b1) {
    asm volatile("mma.sync.aligned.m16n8k16.row.col.f32.f16.f16.f32 "
                 "{%0,%1,%2,%3}, {%4,%5,%6,%7}, {%8,%9}, {%0,%1,%2,%3};\n"
                 : "+f"(c0), "+f"(c1), "+f"(c2), "+f"(c3)
                 : "r"(a0), "r"(a1), "r"(a2), "r"(a3), "r"(b0), "r"(b1));
}

// ---------------- conversion kernels ----------------
__global__ __launch_bounds__(256)
void split_k(const float* __restrict__ in, f16* __restrict__ h,
             f16* __restrict__ l, int n4)
{
    int i = blockIdx.x * blockDim.x + threadIdx.x;
    if (i >= n4) return;
    float4 v = ((const float4*)in)[i];
    f16 hx = __float2half(v.x), hy = __float2half(v.y);
    f16 hz = __float2half(v.z), hw = __float2half(v.w);
    ((f162*)h)[2 * i]     = __halves2half2(hx, hy);
    ((f162*)h)[2 * i + 1] = __halves2half2(hz, hw);
    ((f162*)l)[2 * i] = __halves2half2(
        __float2half(v.x - __half2float(hx)),
        __float2half(v.y - __half2float(hy)));
    ((f162*)l)[2 * i + 1] = __halves2half2(
        __float2half(v.z - __half2float(hz)),
        __float2half(v.w - __half2float(hw)));
}

// Fused hi-only conversion of 4 weight matrices in one launch.
__global__ __launch_bounds__(256)
void split_k1x4(const float* __restrict__ a, f16* __restrict__ ha, int na,
                const float* __restrict__ b, f16* __restrict__ hb, int nb,
                const float* __restrict__ c, f16* __restrict__ hc, int nc,
                const float* __restrict__ d, f16* __restrict__ hd, int nd)
{
    int i = blockIdx.x * blockDim.x + threadIdx.x;
    const float* src; f16* dst;
    if (i < na)                { src = a; dst = ha; }
    else if ((i -= na) < nb)   { src = b; dst = hb; }
    else if ((i -= nb) < nc)   { src = c; dst = hc; }
    else if ((i -= nc) < nd)   { src = d; dst = hd; }
    else return;
    float4 v = ((const float4*)src)[i];
    ((f162*)dst)[2 * i]     = __halves2half2(__float2half(v.x), __float2half(v.y));
    ((f162*)dst)[2 * i + 1] = __halves2half2(__float2half(v.z), __float2half(v.w));
}

// in [z][R][C] fp32 -> out [z][C][R] hi/lo f16 (tiled transpose)
__global__ __launch_bounds__(256)
void transposeSplit(const float* __restrict__ in, f16* __restrict__ outh,
                    f16* __restrict__ outl, int R, int C)
{
    __shared__ float t[32][33];
    const size_t zoff = (size_t)blockIdx.z * R * C;
    in += zoff; outh += zoff; outl += zoff;
    const int c0 = blockIdx.x * 32, r0 = blockIdx.y * 32;
    const int tx = threadIdx.x;
    for (int i = threadIdx.y; i < 32; i += 8)
        t[i][tx] = in[(size_t)(r0 + i) * C + c0 + tx];
    __syncthreads();
    for (int i = threadIdx.y; i < 32; i += 8) {
        float v = t[tx][i];
        f16 hh = __float2half(v);
        outh[(size_t)(c0 + i) * R + r0 + tx] = hh;
        outl[(size_t)(c0 + i) * R + r0 + tx] =
            __float2half(v - __half2float(hh));
    }
}

// in [z][R][C] fp32 -> out [z][C][R] f16 hi only
__global__ __launch_bounds__(256)
void transposeH(const float* __restrict__ in, f16* __restrict__ outh,
                int R, int C)
{
    __shared__ float t[32][33];
    const size_t zoff = (size_t)blockIdx.z * R * C;
    in += zoff; outh += zoff;
    const int c0 = blockIdx.x * 32, r0 = blockIdx.y * 32;
    const int tx = threadIdx.x;
    for (int i = threadIdx.y; i < 32; i += 8)
        t[i][tx] = in[(size_t)(r0 + i) * C + c0 + tx];
    __syncthreads();
    for (int i = threadIdx.y; i < 32; i += 8)
        outh[(size_t)(c0 + i) * R + r0 + tx] = __float2half(t[tx][i]);
}

// ---------------- split-fp16 NT GEMM (cp.async pipelined) ----------------
// C[M,N] = A @ B^T, fp32 acc, cp.async pipeline, CTA (MW*64)x128, BK=32.
// MW: 2 -> 128x128 CTA (4 warps, 2 CTAs/SM); 4 -> 256x128 (8 warps, 1 CTA/SM).
// NPASS=2: A=(Ah+Al), B=Bh, 2 passes, 3 stages. NPASS=1: single pass, 4 stages.
// OMODE: 0 = fp32 C, 1 = hi/lo f16 C, 2 = hi-only f16 C.
// mode: 0 plain; 1 causal tile skip; 2 K-cap at (y+1)*MROWS;
//       3 PAIR-BALANCED K-cap: CTA does m-tiles y and (2*gridDim.y-1-y).
// Tail wait is remaining-groups aware.
// BhAlt/CAlt: when non-null and blockIdx.z==1, swap B/C pointers (fused dual GEMM).
#define LDSP 40                    // padded row in f16 elems (80B)
#define ROWB (LDSP * 2)            // 80
#define BTILEB (128 * ROWB)        // 10240

template <int OMODE, int NPASS, int MW>
__global__ __launch_bounds__(MW * 64, 4 / MW)
void gemm2(const f16* __restrict__ Ah, const f16* __restrict__ Al,
           int lda, long long sA,
           const f16* __restrict__ Bh,
           int ldb, long long sB,
           void* __restrict__ Cp0, void* __restrict__ Cp1,
           int ldc, long long sC, int K, int mode,
           const f16* __restrict__ BhAlt,
           void* __restrict__ CAlt0, void* __restrict__ CAlt1)
{
    constexpr int MROWS = MW * 64;
    if (mode == 1 && (int)(blockIdx.x * 128) >= (int)((blockIdx.y + 1) * MROWS)) return;

    constexpr int ATILEB = MROWS * ROWB;
    constexpr int STAGES = (NPASS == 1) ? 4 : 3;
    constexpr int STAGEB = ((NPASS == 2) ? 2 : 1) * ATILEB + BTILEB;
    constexpr uint32_t O_AH = 0;
    constexpr uint32_t O_AL = ATILEB;                      // only if NPASS==2
    constexpr uint32_t O_BH = ((NPASS == 2) ? 2 : 1) * ATILEB;

    extern __shared__ char smem[];
    const uint32_t sbase = smem_u32(smem);
    const int tid = threadIdx.x;
    const int lane = tid & 31;
    const int wid = tid >> 5;
    const int wm = (wid >> 1) * 64;
    const int wn = (wid & 1) * 64;

    if (BhAlt && blockIdx.z) {
        Bh = BhAlt; Cp0 = CAlt0; Cp1 = CAlt1;
    }
    Ah += (long long)blockIdx.z * sA;
    if (NPASS == 2) Al += (long long)blockIdx.z * sA;
    Bh += (long long)blockIdx.z * sB;
    const int n0 = blockIdx.x * 128;

    const int row = tid >> 2;      // 0 .. MW*16-1
    const int ch = tid & 3;

    const int ntile = (mode == 3) ? 2 : 1;

    for (int ti = 0; ti < ntile; ++ti) {
        const int yb = (ti == 0) ? (int)blockIdx.y
                                 : (int)(2 * gridDim.y - 1 - blockIdx.y);
        const int m0 = yb * MROWS;

        int nIter = K >> 5;
        if (mode == 2 || mode == 3) {
            int kc = (yb + 1) * MROWS;
            if (kc < K) nIter = kc >> 5;
        }

        if (ti) __syncthreads();   // protect smem stages between tiles

        auto issue = [&](int g) {
            const int k0 = g << 5;
            const uint32_t sb = sbase + (g % STAGES) * STAGEB;
            #pragma unroll
            for (int i = 0; i < 4; ++i) {                      // A: MROWS rows
                int r = row + i * (MW * 16);
                uint32_t doff = (uint32_t)(r * ROWB + ch * 16);
                cp16(sb + O_AH + doff, Ah + (size_t)(m0 + r) * lda + k0 + ch * 8);
                if (NPASS == 2)
                    cp16(sb + O_AL + doff, Al + (size_t)(m0 + r) * lda + k0 + ch * 8);
            }
            #pragma unroll
            for (int i = 0; i < 8 / MW; ++i) {                 // B: 128 rows
                int r = row + i * (MW * 16);
                uint32_t doff = (uint32_t)(r * ROWB + ch * 16);
                cp16(sb + O_BH + doff, Bh + (size_t)(n0 + r) * ldb + k0 + ch * 8);
            }
            cp_commit();
        };

        float acc[4][8][4] = {};

        #pragma unroll
        for (int s = 0; s < STAGES - 1; ++s)
            if (s < nIter) issue(s);

        for (int it = 0; it < nIter; ++it) {
            // Tail-aware wait: allowable pending = min(STAGES-2, nIter-1-it).
            {
                int rem = nIter - 1 - it;
                if (rem >= STAGES - 2) cp_wait<STAGES - 2>();
                else if (rem == 1)     cp_wait<1>();
                else                   cp_wait<0>();
            }
            __syncthreads();

            const uint32_t sb = sbase + (it % STAGES) * STAGEB;
            #pragma unroll
            for (int kk = 0; kk < 32; kk += 16) {
                uint32_t Ahf[4][4], Alf[4][4], Bhf[8][2];

                const uint32_t abase =
                    (uint32_t)(((wm + (lane & 15)) * LDSP + kk + ((lane >> 4) << 3)) * 2);
                #pragma unroll
                for (int mi = 0; mi < 4; ++mi) {
                    ldsm_x4(Ahf[mi][0], Ahf[mi][1], Ahf[mi][2], Ahf[mi][3],
                            sb + O_AH + abase + (uint32_t)(mi * 16 * ROWB));
                    if (NPASS == 2)
                        ldsm_x4(Alf[mi][0], Alf[mi][1], Alf[mi][2], Alf[mi][3],
                                sb + O_AL + abase + (uint32_t)(mi * 16 * ROWB));
                }
                const uint32_t bbase =
                    (uint32_t)(((wn + ((lane >> 4) << 3) + (lane & 7)) * LDSP +
                                kk + (((lane >> 3) & 1) << 3)) * 2);
                #pragma unroll
                for (int nt = 0; nt < 4; ++nt) {
                    ldsm_x4(Bhf[2 * nt][0], Bhf[2 * nt][1],
                            Bhf[2 * nt + 1][0], Bhf[2 * nt + 1][1],
                            sb + O_BH + bbase + (uint32_t)(nt * 16 * ROWB));
                }

                #pragma unroll
                for (int mi = 0; mi < 4; ++mi)
                    #pragma unroll
                    for (int ni = 0; ni < 8; ++ni)
                        mma_f16(acc[mi][ni][0], acc[mi][ni][1], acc[mi][ni][2], acc[mi][ni][3],
                                Ahf[mi][0], Ahf[mi][1], Ahf[mi][2], Ahf[mi][3],
                                Bhf[ni][0], Bhf[ni][1]);
                if (NPASS == 2) {
                    #pragma unroll
                    for (int mi = 0; mi < 4; ++mi)
                        #pragma unroll
                        for (int ni = 0; ni < 8; ++ni)
                            mma_f16(acc[mi][ni][0], acc[mi][ni][1], acc[mi][ni][2], acc[mi][ni][3],
                                    Alf[mi][0], Alf[mi][1], Alf[mi][2], Alf[mi][3],
                                    Bhf[ni][0], Bhf[ni][1]);
                }
            }
            if (it + STAGES - 1 < nIter) issue(it + STAGES - 1);
        }

        // ---- epilogue ----
        if (OMODE == 0) {
            float* C = (float*)Cp0 + (long long)blockIdx.z * sC;
            #pragma unroll
            for (int mi = 0; mi < 4; ++mi) {
                #pragma unroll
                for (int ni = 0; ni < 8; ++ni) {
                    int r = m0 + wm + mi * 16 + (lane >> 2);
                    int c = n0 + wn + ni * 8 + (lane & 3) * 2;
                    *(float2*)&C[(size_t)r * ldc + c] =
                        make_float2(acc[mi][ni][0], acc[mi][ni][1]);
                    *(float2*)&C[(size_t)(r + 8) * ldc + c] =
                        make_float2(acc[mi][ni][2], acc[mi][ni][3]);
                }
            }
        } else {
            f16* Ch = (f16*)Cp0 + (long long)blockIdx.z * sC;
            f16* Cl = (OMODE == 1) ? (f16*)Cp1 + (long long)blockIdx.z * sC : nullptr;
            #pragma unroll
            for (int mi = 0; mi < 4; ++mi) {
                #pragma unroll
                for (int ni = 0; ni < 8; ++ni) {
                    int r = m0 + wm + mi * 16 + (lane >> 2);
                    int c = n0 + wn + ni * 8 + (lane & 3) * 2;
                    #pragma unroll
                    for (int half = 0; half < 2; ++half) {
                        float a0 = acc[mi][ni][2 * half], a1 = acc[mi][ni][2 * half + 1];
                        f16 h0 = __float2half(a0), h1 = __float2half(a1);
                        size_t off = (size_t)(r + half * 8) * ldc + c;
                        *(f162*)&Ch[off] = __halves2half2(h0, h1);
                        if (OMODE == 1)
                            *(f162*)&Cl[off] = __halves2half2(
                                __float2half(a0 - __half2float(h0)),
                                __float2half(a1 - __half2float(h1)));
                    }
                }
            }
        }
    }
}

// ---------------- masked softmax (reads hi/lo logits, writes hi probs) -----
// Zero-fills probs out to a 256-aligned bound so 256-granule K-caps in the
// attn*V GEMM never see raw logits.
__global__ __launch_bounds__(256)
void softmax2(f16* __restrict__ Sh, f16* __restrict__ Sl)
{
    const int t = blockIdx.x;
    const int h = blockIdx.y;
    f162* rowh = (f162*)(Sh + ((size_t)h * TT + t) * TT);
    f162* rowl = (f162*)(Sl + ((size_t)h * TT + t) * TT);

    const float inv = 0.044194173824159216f; // 1/sqrt(512)
    const int tid = threadIdx.x;
    const int boundp = (((t >> 8) + 1) << 8) >> 1;  // 256-aligned, in pairs

    __shared__ float red[256];

    float vals[8];
    float lmax = -INFINITY;
    #pragma unroll
    for (int i = 0; i < 4; ++i) {
        int sp = tid + i * 256;
        if (sp >= boundp) break;
        int s = sp * 2;
        float v0 = -INFINITY, v1 = -INFINITY;
        if (s <= t) {
            float2 vh = __half22float2(rowh[sp]);
            float2 vl = __half22float2(rowl[sp]);
            v0 = (vh.x + vl.x) * inv;
            if (t - s < RA_WIN) v0 *= 1.5f;
            lmax = fmaxf(lmax, v0);
            if (s + 1 <= t) {
                v1 = (vh.y + vl.y) * inv;
                if (t - (s + 1) < RA_WIN) v1 *= 1.5f;
                lmax = fmaxf(lmax, v1);
            }
        }
        vals[2 * i] = v0;
        vals[2 * i + 1] = v1;
    }
    red[tid] = lmax;
    __syncthreads();
    #pragma unroll
    for (int o = 128; o > 0; o >>= 1) {
        if (tid < o) red[tid] = fmaxf(red[tid], red[tid + o]);
        __syncthreads();
    }
    const float m = red[0];
    __syncthreads();

    float lsum = 0.f;
    #pragma unroll
    for (int i = 0; i < 4; ++i) {
        int sp = tid + i * 256;
        if (sp >= boundp) break;
        int s = sp * 2;
        float e0 = 0.f, e1 = 0.f;
        if (s <= t)     { e0 = __expf(vals[2 * i] - m);     lsum += e0; }
        if (s + 1 <= t) { e1 = __expf(vals[2 * i + 1] - m); lsum += e1; }
        vals[2 * i] = e0;
        vals[2 * i + 1] = e1;
    }
    red[tid] = lsum;
    __syncthreads();
    #pragma unroll
    for (int o = 128; o > 0; o >>= 1) {
        if (tid < o) red[tid] += red[tid + o];
        __syncthreads();
    }
    const float inv_sum = 1.0f / red[0];

    #pragma unroll
    for (int i = 0; i < 4; ++i) {
        int sp = tid + i * 256;
        if (sp >= boundp) break;
        rowh[sp] = __halves2half2(
            __float2half(vals[2 * i] * inv_sum),
            __float2half(vals[2 * i + 1] * inv_sum));
    }
}

// ---------------- launch ----------------
extern "C" void kernel_launch(void* const* d_in, const int* in_sizes, int n_in,
                              void* d_out, int out_size)
{
    const float* hidden = (const float*)d_in[0]; // [T, E]
    const float* w_q    = (const float*)d_in[1]; // [E, E]
    const float* w_kd   = (const float*)d_in[2]; // [L, E]
    const float* w_vd   = (const float*)d_in[3]; // [L, E]
    const float* q2l    = (const float*)d_in[4]; // [H, D, L]
    const float* v_up   = (const float*)d_in[5]; // [H, L, D]
    const float* w_out  = (const float*)d_in[6]; // [E, E]
    float* out = (float*)d_out;                  // [T, E]

    f16 *hidh, *hidl, *wqh, *wkdh, *wvdh, *wouth, *q2lTh, *vupTh, *vupTl;
    f16 *Qh, *Ql, *latkh, *latvh, *qlath, *qlatl;
    f16 *VTh, *Sh, *Sl, *ctxh;
    cudaGetSymbolAddress((void**)&hidh, g_hidh);   cudaGetSymbolAddress((void**)&hidl, g_hidl);
    cudaGetSymbolAddress((void**)&wqh, g_wqh);
    cudaGetSymbolAddress((void**)&wkdh, g_wkdh);
    cudaGetSymbolAddress((void**)&wvdh, g_wvdh);
    cudaGetSymbolAddress((void**)&wouth, g_wouth);
    cudaGetSymbolAddress((void**)&q2lTh, g_q2lTh);
    cudaGetSymbolAddress((void**)&vupTh, g_vupTh); cudaGetSymbolAddress((void**)&vupTl, g_vupTl);
    cudaGetSymbolAddress((void**)&Qh, g_Qh);       cudaGetSymbolAddress((void**)&Ql, g_Ql);
    cudaGetSymbolAddress((void**)&latkh, g_latkh);
    cudaGetSymbolAddress((void**)&latvh, g_latvh);
    cudaGetSymbolAddress((void**)&qlath, g_qlath); cudaGetSymbolAddress((void**)&qlatl, g_qlatl);
    cudaGetSymbolAddress((void**)&VTh, g_VTh);
    cudaGetSymbolAddress((void**)&Sh, g_Sh);       cudaGetSymbolAddress((void**)&Sl, g_Sl);
    cudaGetSymbolAddress((void**)&ctxh, g_ctxh);

    // smem sizes
    const int SM_2_2 = 3 * (2 * 128 * ROWB + BTILEB);   // 92160
    const int SM_2_4 = 3 * (2 * 256 * ROWB + BTILEB);   // 153600
    const int SM_1_2 = 4 * (1 * 128 * ROWB + BTILEB);   // 81920 (4-stage)
    cudaFuncSetAttribute(gemm2<1, 2, 2>, cudaFuncAttributeMaxDynamicSharedMemorySize, SM_2_2);
    cudaFuncSetAttribute(gemm2<2, 2, 2>, cudaFuncAttributeMaxDynamicSharedMemorySize, SM_2_2);
    cudaFuncSetAttribute(gemm2<1, 2, 4>, cudaFuncAttributeMaxDynamicSharedMemorySize, SM_2_4);
    cudaFuncSetAttribute(gemm2<2, 1, 2>, cudaFuncAttributeMaxDynamicSharedMemorySize, SM_1_2);
    cudaFuncSetAttribute(gemm2<0, 1, 2>, cudaFuncAttributeMaxDynamicSharedMemorySize, SM_1_2);

    // ---- conversions ----
    split_k<<<(TT * EE / 4 + 255) / 256, 256>>>(hidden, hidh, hidl, TT * EE / 4);
    {
        const int na = EE * EE / 4, nb = LL * EE / 4, nc = LL * EE / 4, nd = EE * EE / 4;
        split_k1x4<<<(na + nb + nc + nd + 255) / 256, 256>>>(
            w_q, wqh, na, w_kd, wkdh, nb, w_vd, wvdh, nc, w_out, wouth, nd);
    }
    transposeH<<<dim3(LL / 32, DD / 32, HH), dim3(32, 8)>>>(q2l, q2lTh, DD, LL);
    transposeSplit<<<dim3(DD / 32, LL / 32, HH), dim3(32, 8)>>>(v_up, vupTh, vupTl, LL, DD);

    // 1) Q = hidden @ w_q^T  [2048,2048,2048]  (2-pass, hi/lo out, MW=2 for fill)
    gemm2<1, 2, 2><<<dim3(EE / 128, TT / 128, 1), dim3(128), SM_2_2>>>(
        hidh, hidl, EE, 0, wqh, EE, 0, Qh, Ql, EE, 0, EE, 0,
        nullptr, nullptr, nullptr);

    // 2+3) latent_k / latent_v fused (z=0 -> latk, z=1 -> latv), 2-pass, hi-only
    gemm2<2, 2, 2><<<dim3(LL / 128, TT / 128, 2), dim3(128), SM_2_2>>>(
        hidh, hidl, EE, 0, wkdh, EE, 0, latkh, nullptr, LL, 0, EE, 0,
        wvdh, latvh, nullptr);

    // 4) q_latent[h] = Q[:,hD:] @ q2lT[h]^T  [2048,512,128]  (2-pass, hi/lo)
    gemm2<1, 2, 2><<<dim3(LL / 128, TT / 128, HH), dim3(128), SM_2_2>>>(
        Qh, Ql, EE, DD, q2lTh, DD, (long long)LL * DD,
        qlath, qlatl, LL, (long long)TT * LL, DD, 0,
        nullptr, nullptr, nullptr);

    // 5) VT[h] = vupT[h] @ latv^T  [128,2048,512]  (2-pass, direct V^T)
    gemm2<2, 2, 2><<<dim3(TT / 128, 1, HH), dim3(128), SM_2_2>>>(
        vupTh, vupTl, LL, (long long)DD * LL, latvh, LL, 0,
        VTh, nullptr, TT, (long long)DD * TT, LL, 0,
        nullptr, nullptr, nullptr);

    // 6) S[h] = q_latent[h] @ latent_k^T  [2048,2048,512]
    //    causal tile skip, 2-pass, hi/lo logits out, 256-tile (many waves)
    gemm2<1, 2, 4><<<dim3(TT / 128, TT / 256, HH), dim3(256), SM_2_4>>>(
        qlath, qlatl, LL, (long long)TT * LL, latkh, LL, 0,
        Sh, Sl, TT, (long long)TT * TT, LL, 1,
        nullptr, nullptr, nullptr);

    // 7) masked softmax: read hi/lo logits, write hi probs, 256-aligned bound
    softmax2<<<dim3(TT, HH), dim3(256)>>>(Sh, Sl);

    // 8) ctx[:,h] = attn[h] @ VT[h]^T  [2048,128,2048]
    //    PAIR-BALANCED K-cap (mode 3), 1-pass, hi-only ctx out, 4-stage
    gemm2<2, 1, 2><<<dim3(DD / 128, TT / 256, HH), dim3(128), SM_1_2>>>(
        Sh, nullptr, TT, (long long)TT * TT, VTh, TT, (long long)DD * TT,
        ctxh, nullptr, EE, DD, TT, 3,
        nullptr, nullptr, nullptr);

    // 9) out = ctx @ w_out^T  [2048,2048,2048]  (1-pass, fp32 out, MW=2 for fill)
    gemm2<0, 1, 2><<<dim3(EE / 128, TT / 128, 1), dim3(128), SM_1_2>>>(
        ctxh, nullptr, EE, 0, wouth, EE, 0, out, nullptr, EE, 0, EE, 0,
        nullptr, nullptr, nullptr);
}